// round 2
// baseline (speedup 1.0000x reference)
#include <cuda_runtime.h>
#include <math.h>

// Problem constants: N=50000, E=400000, d=64
#define MAXN 50000
#define MAXE 400000

// ---------------- static scratch ----------------
__device__ float g_agg0[MAXN * 64];    // P @ x
__device__ float g_T1[MAXN * 256];     // tanh((Px)[W1|W3]+b) ; later reused as H[n,128]
__device__ float g_agg1[MAXN * 256];   // P @ T1
__device__ float g_U[MAXN * 256];      // conv2 output (for colmax)
__device__ float g_V[MAXN * 256];      // conv4 output
__device__ float g_dis[MAXN];
__device__ int   g_cnt[MAXN];
__device__ int   g_rowptr[MAXN + 1];
__device__ int   g_cursor[MAXN];
__device__ int   g_csrsrc[MAXE];
__device__ float g_csrnorm[MAXE];
__device__ int   g_mv[256];
__device__ float g_cvec[128];
__device__ float g_Wc[64 * 256];       // [W1 | W3]
__device__ float g_bc[256];            // [b1 | b3]

// ---------------- degree count ----------------
__global__ void count_kernel(const int* __restrict__ dst, int e, int* __restrict__ cnt) {
    int i = blockIdx.x * blockDim.x + threadIdx.x;
    if (i < e) atomicAdd(&cnt[dst[i]], 1);
}

// ---------------- single-block scan + dis ----------------
__global__ void scan_kernel(const int* __restrict__ cnt, int n,
                            int* __restrict__ rowptr, int* __restrict__ cursor,
                            float* __restrict__ dis) {
    __shared__ int sh[1024];
    int tid = threadIdx.x;
    int run = 0;
    for (int base = 0; base < n; base += 1024) {
        int i = base + tid;
        int v = (i < n) ? cnt[i] : 0;
        sh[tid] = v;
        __syncthreads();
        int val = v;
        for (int off = 1; off < 1024; off <<= 1) {
            int t = (tid >= off) ? sh[tid - off] : 0;
            __syncthreads();
            val += t;
            sh[tid] = val;
            __syncthreads();
        }
        if (i < n) {
            int excl = run + val - v;
            rowptr[i] = excl;
            cursor[i] = excl;
            dis[i] = rsqrtf((float)(v + 1));
        }
        int tot = sh[1023];
        __syncthreads();
        run += tot;
    }
    if (tid == 0) rowptr[n] = run;
}

// ---------------- CSR fill ----------------
__global__ void fill_kernel(const int* __restrict__ src, const int* __restrict__ dst, int e,
                            int* __restrict__ cursor, int* __restrict__ csrsrc,
                            float* __restrict__ csrnorm, const float* __restrict__ dis) {
    int i = blockIdx.x * blockDim.x + threadIdx.x;
    if (i >= e) return;
    int d = dst[i];
    int s = src[i];
    int p = atomicAdd(&cursor[d], 1);
    csrsrc[p] = s;
    csrnorm[p] = dis[s] * dis[d];
}

// ---------------- pack [W1|W3], [b1|b3] ----------------
__global__ void pack_kernel(const float* __restrict__ W1, const float* __restrict__ W3,
                            const float* __restrict__ b1, const float* __restrict__ b3,
                            float* __restrict__ Wc, float* __restrict__ bc) {
    int i = blockIdx.x * blockDim.x + threadIdx.x;
    if (i < 64 * 256) {
        int k = i >> 8, c = i & 255;
        Wc[i] = (c < 128) ? W1[k * 128 + c] : W3[k * 128 + (c - 128)];
    }
    if (i < 256) bc[i] = (i < 128) ? b1[i] : b3[i - 128];
}

// ---------------- packed f32x2 FMA ----------------
__device__ __forceinline__ void ffma2(unsigned long long& d, unsigned long long a,
                                      unsigned long long b) {
    asm("fma.rn.f32x2 %0, %1, %2, %0;" : "+l"(d) : "l"(a), "l"(b));
}

union F2U { unsigned long long u; float2 f; };

// ---------------- f32x2 SGEMM: C = act(A[n,K;lda] @ W[K,ncol] + addvec) ----
// BM=128, BN=128, BK=8, 256 threads, 8x8 per thread via row-paired f32x2.
#define AS_STRIDE 132
#define BS_STRIDE 264
__global__ __launch_bounds__(256, 2)
void sgemm2_kernel(const float* __restrict__ A, int lda,
                   const float* __restrict__ W,
                   float* __restrict__ C,
                   int n, int K, int ncol,
                   const float* __restrict__ addvec,
                   int accumulate, int dotanh) {
    __shared__ __align__(16) float As[8 * AS_STRIDE];
    __shared__ __align__(16) float Bs[8 * BS_STRIDE];  // duplicated columns
    int tid = threadIdx.x;
    int tx = tid & 15, ty = tid >> 4;
    int rowBase = blockIdx.x * 128;
    int colBase = blockIdx.y * 128;

    int aRow = tid >> 1;
    int aOff = (tid & 1) * 4;
    int bK = tid >> 5;
    int bCol = (tid & 31) * 4;

    unsigned long long acc[4][8];
#pragma unroll
    for (int i = 0; i < 4; i++)
#pragma unroll
        for (int j = 0; j < 8; j++) acc[i][j] = 0ull;

    bool aValid = (rowBase + aRow) < n;
    const float* aPtr = A + (size_t)(rowBase + aRow) * lda + aOff;
    const float* wPtr = W + (size_t)bK * ncol + colBase + bCol;

    for (int k0 = 0; k0 < K; k0 += 8) {
        float4 av = aValid ? *(const float4*)(aPtr + k0) : make_float4(0.f, 0.f, 0.f, 0.f);
        float4 wv = *(const float4*)(wPtr + (size_t)k0 * ncol);
        __syncthreads();
        As[(aOff + 0) * AS_STRIDE + aRow] = av.x;
        As[(aOff + 1) * AS_STRIDE + aRow] = av.y;
        As[(aOff + 2) * AS_STRIDE + aRow] = av.z;
        As[(aOff + 3) * AS_STRIDE + aRow] = av.w;
        float* bp = &Bs[bK * BS_STRIDE + 2 * bCol];
        *(float4*)(bp + 0) = make_float4(wv.x, wv.x, wv.y, wv.y);
        *(float4*)(bp + 4) = make_float4(wv.z, wv.z, wv.w, wv.w);
        __syncthreads();

#pragma unroll
        for (int k = 0; k < 8; k++) {
            const ulonglong2* ap = (const ulonglong2*)&As[k * AS_STRIDE + ty * 8];
            ulonglong2 a01 = ap[0], a23 = ap[1];
            const ulonglong2* bq = (const ulonglong2*)&Bs[k * BS_STRIDE + tx * 16];
            ulonglong2 b01 = bq[0], b23 = bq[1], b45 = bq[2], b67 = bq[3];
            unsigned long long ra[4] = {a01.x, a01.y, a23.x, a23.y};
            unsigned long long rb[8] = {b01.x, b01.y, b23.x, b23.y,
                                        b45.x, b45.y, b67.x, b67.y};
#pragma unroll
            for (int rp = 0; rp < 4; rp++)
#pragma unroll
                for (int c = 0; c < 8; c++) ffma2(acc[rp][c], ra[rp], rb[c]);
        }
    }

    // epilogue
    float av0[4] = {0.f, 0.f, 0.f, 0.f}, av1[4] = {0.f, 0.f, 0.f, 0.f};
    if (addvec) {
        float4 t0 = *(const float4*)(addvec + colBase + tx * 8);
        float4 t1 = *(const float4*)(addvec + colBase + tx * 8 + 4);
        av0[0] = t0.x; av0[1] = t0.y; av0[2] = t0.z; av0[3] = t0.w;
        av1[0] = t1.x; av1[1] = t1.y; av1[2] = t1.z; av1[3] = t1.w;
    }
#pragma unroll
    for (int rp = 0; rp < 4; rp++) {
#pragma unroll
        for (int h = 0; h < 2; h++) {
            int row = rowBase + ty * 8 + rp * 2 + h;
            if (row >= n) continue;
            float v[8];
#pragma unroll
            for (int c = 0; c < 8; c++) {
                F2U t; t.u = acc[rp][c];
                v[c] = h ? t.f.y : t.f.x;
            }
#pragma unroll
            for (int c = 0; c < 4; c++) { v[c] += av0[c]; v[c + 4] += av1[c]; }
            float* cp = C + (size_t)row * ncol + colBase + tx * 8;
            if (accumulate) {
                float4 p0 = *(const float4*)cp;
                float4 p1 = *(const float4*)(cp + 4);
                v[0] += p0.x; v[1] += p0.y; v[2] += p0.z; v[3] += p0.w;
                v[4] += p1.x; v[5] += p1.y; v[6] += p1.z; v[7] += p1.w;
            }
            if (dotanh) {
#pragma unroll
                for (int c = 0; c < 8; c++) v[c] = tanhf(v[c]);
            }
            *(float4*)cp = make_float4(v[0], v[1], v[2], v[3]);
            *(float4*)(cp + 4) = make_float4(v[4], v[5], v[6], v[7]);
        }
    }
}

// ---------------- agg F=64: out = P h (raw) ----------------
__global__ void agg64_kernel(const float* __restrict__ h, const int* __restrict__ rowptr,
                             const int* __restrict__ csrsrc, const float* __restrict__ csrnorm,
                             const float* __restrict__ dis, float* __restrict__ out, int n) {
    int warp = (blockIdx.x * blockDim.x + threadIdx.x) >> 5;
    int lane = threadIdx.x & 31;
    if (warp >= n) return;
    float2 acc = make_float2(0.f, 0.f);
    int s0 = rowptr[warp], s1 = rowptr[warp + 1];
    int j = s0;
    for (; j + 1 < s1; j += 2) {
        int sa = csrsrc[j], sb = csrsrc[j + 1];
        float wa = csrnorm[j], wb = csrnorm[j + 1];
        float2 va = *(const float2*)(h + (size_t)sa * 64 + lane * 2);
        float2 vb = *(const float2*)(h + (size_t)sb * 64 + lane * 2);
        acc.x += va.x * wa + vb.x * wb;
        acc.y += va.y * wa + vb.y * wb;
    }
    if (j < s1) {
        int s = csrsrc[j];
        float w = csrnorm[j];
        float2 va = *(const float2*)(h + (size_t)s * 64 + lane * 2);
        acc.x += va.x * w;
        acc.y += va.y * w;
    }
    float ds = dis[warp];
    float w2 = ds * ds;
    float2 v = *(const float2*)(h + (size_t)warp * 64 + lane * 2);
    acc.x += v.x * w2;
    acc.y += v.y * w2;
    *(float2*)(out + (size_t)warp * 64 + lane * 2) = acc;
}

// ---------------- agg F=256: out = P h (raw) ----------------
__global__ void agg256_kernel(const float* __restrict__ h, const int* __restrict__ rowptr,
                              const int* __restrict__ csrsrc, const float* __restrict__ csrnorm,
                              const float* __restrict__ dis, float* __restrict__ out, int n) {
    int warp = (blockIdx.x * blockDim.x + threadIdx.x) >> 5;
    int lane = threadIdx.x & 31;
    if (warp >= n) return;
    float4 a0 = make_float4(0.f, 0.f, 0.f, 0.f), a1 = a0;
    int s0 = rowptr[warp], s1 = rowptr[warp + 1];
    int i0 = lane << 2, i1 = (lane + 32) << 2;
    for (int j = s0; j < s1; j++) {
        int s = csrsrc[j];
        float w = csrnorm[j];
        const float* hp = h + (size_t)s * 256;
        float4 v0 = *(const float4*)(hp + i0);
        float4 v1 = *(const float4*)(hp + i1);
        a0.x += v0.x * w; a0.y += v0.y * w; a0.z += v0.z * w; a0.w += v0.w * w;
        a1.x += v1.x * w; a1.y += v1.y * w; a1.z += v1.z * w; a1.w += v1.w * w;
    }
    float ds = dis[warp];
    float w2 = ds * ds;
    const float* hp = h + (size_t)warp * 256;
    float4 v0 = *(const float4*)(hp + i0);
    float4 v1 = *(const float4*)(hp + i1);
    a0.x += v0.x * w2; a0.y += v0.y * w2; a0.z += v0.z * w2; a0.w += v0.w * w2;
    a1.x += v1.x * w2; a1.y += v1.y * w2; a1.z += v1.z * w2; a1.w += v1.w * w2;
    float* op = out + (size_t)warp * 256;
    *(float4*)(op + i0) = a0;
    *(float4*)(op + i1) = a1;
}

// ---------------- agg F=128 + bias + tanh (final) ----------------
__global__ void agg128t_kernel(const float* __restrict__ h, const int* __restrict__ rowptr,
                               const int* __restrict__ csrsrc, const float* __restrict__ csrnorm,
                               const float* __restrict__ dis, const float* __restrict__ bias,
                               float* __restrict__ out, int n) {
    int warp = (blockIdx.x * blockDim.x + threadIdx.x) >> 5;
    int lane = threadIdx.x & 31;
    if (warp >= n) return;
    float4 acc = make_float4(0.f, 0.f, 0.f, 0.f);
    int s0 = rowptr[warp], s1 = rowptr[warp + 1];
    int idx = lane << 2;
    int j = s0;
    for (; j + 1 < s1; j += 2) {
        int sa = csrsrc[j], sb = csrsrc[j + 1];
        float wa = csrnorm[j], wb = csrnorm[j + 1];
        float4 va = *(const float4*)(h + (size_t)sa * 128 + idx);
        float4 vb = *(const float4*)(h + (size_t)sb * 128 + idx);
        acc.x += va.x * wa + vb.x * wb;
        acc.y += va.y * wa + vb.y * wb;
        acc.z += va.z * wa + vb.z * wb;
        acc.w += va.w * wa + vb.w * wb;
    }
    if (j < s1) {
        int s = csrsrc[j];
        float w = csrnorm[j];
        float4 va = *(const float4*)(h + (size_t)s * 128 + idx);
        acc.x += va.x * w; acc.y += va.y * w; acc.z += va.z * w; acc.w += va.w * w;
    }
    float ds = dis[warp];
    float w2 = ds * ds;
    float4 v = *(const float4*)(h + (size_t)warp * 128 + idx);
    float4 bb = *(const float4*)(bias + idx);
    float4 r;
    r.x = tanhf(acc.x + v.x * w2 + bb.x);
    r.y = tanhf(acc.y + v.y * w2 + bb.y);
    r.z = tanhf(acc.z + v.z * w2 + bb.z);
    r.w = tanhf(acc.w + v.w * w2 + bb.w);
    *(float4*)(out + (size_t)warp * 128 + idx) = r;
}

// ---------------- column max over U[n,256] ----------------
__global__ void colmax_kernel(const float* __restrict__ B, int n, int* __restrict__ mv) {
    int col = threadIdx.x;
    float m = -1e30f;
    for (int r = blockIdx.x; r < n; r += gridDim.x)
        m = fmaxf(m, B[(size_t)r * 256 + col]);
    atomicMax(&mv[col], __float_as_int(m + 2.0f));
}

// ---------------- cvec = mv @ W7[0:256,:] ----------------
__global__ void cvec_kernel(const int* __restrict__ mv, const float* __restrict__ W7,
                            float* __restrict__ cvec) {
    int j = threadIdx.x;
    float s = 0.0f;
    for (int k = 0; k < 256; k++)
        s += (__int_as_float(mv[k]) - 2.0f) * W7[(size_t)k * 128 + j];
    cvec[j] = s;
}

extern "C" void kernel_launch(void* const* d_in, const int* in_sizes, int n_in,
                              void* d_out, int out_size) {
    const float* x  = (const float*)d_in[0];
    const int*   ei = (const int*)d_in[1];
    const float* W1 = (const float*)d_in[3];
    const float* b1 = (const float*)d_in[4];
    const float* W2 = (const float*)d_in[5];
    const float* b2 = (const float*)d_in[6];
    const float* W3 = (const float*)d_in[7];
    const float* b3 = (const float*)d_in[8];
    const float* W4 = (const float*)d_in[9];
    const float* b4 = (const float*)d_in[10];
    const float* W7 = (const float*)d_in[11];
    const float* b7 = (const float*)d_in[12];

    int n = in_sizes[0] / 64;
    int e = in_sizes[1] / 2;
    const int* src = ei;
    const int* dst = ei + e;
    float* out = (float*)d_out;

    float *agg0, *T1, *agg1, *U, *V, *dis, *csrnorm, *cvec, *Wc, *bc;
    int *cnt, *rowptr, *cursor, *csrsrc, *mv;
    cudaGetSymbolAddress((void**)&agg0, g_agg0);
    cudaGetSymbolAddress((void**)&T1, g_T1);
    cudaGetSymbolAddress((void**)&agg1, g_agg1);
    cudaGetSymbolAddress((void**)&U, g_U);
    cudaGetSymbolAddress((void**)&V, g_V);
    cudaGetSymbolAddress((void**)&dis, g_dis);
    cudaGetSymbolAddress((void**)&cnt, g_cnt);
    cudaGetSymbolAddress((void**)&rowptr, g_rowptr);
    cudaGetSymbolAddress((void**)&cursor, g_cursor);
    cudaGetSymbolAddress((void**)&csrsrc, g_csrsrc);
    cudaGetSymbolAddress((void**)&csrnorm, g_csrnorm);
    cudaGetSymbolAddress((void**)&mv, g_mv);
    cudaGetSymbolAddress((void**)&cvec, g_cvec);
    cudaGetSymbolAddress((void**)&Wc, g_Wc);
    cudaGetSymbolAddress((void**)&bc, g_bc);

    float* H = T1;  // reuse: T1 is dead after agg1

    int eb = (e + 255) / 256;
    int aggBlocks = (n + 7) / 8;  // 256 threads = 8 warps, 1 warp/node
    dim3 g256((n + 127) / 128, 2);
    dim3 g128((n + 127) / 128, 1);

    // CSR build + weight pack
    cudaMemsetAsync(cnt, 0, (size_t)n * sizeof(int));
    pack_kernel<<<64, 256>>>(W1, W3, b1, b3, Wc, bc);
    count_kernel<<<eb, 256>>>(dst, e, cnt);
    scan_kernel<<<1, 1024>>>(cnt, n, rowptr, cursor, dis);
    fill_kernel<<<eb, 256>>>(src, dst, e, cursor, csrsrc, csrnorm, dis);

    // agg0 = P x   (shared by conv1 & conv3)
    agg64_kernel<<<aggBlocks, 256>>>(x, rowptr, csrsrc, csrnorm, dis, agg0, n);
    // T1 = tanh(agg0 @ [W1|W3] + [b1|b3])   (conv1 || conv3)
    sgemm2_kernel<<<g256, 256>>>(agg0, 64, Wc, T1, n, 64, 256, bc, 0, 1);
    // agg1 = P T1  (one fused 256-wide pass)
    agg256_kernel<<<aggBlocks, 256>>>(T1, rowptr, csrsrc, csrnorm, dis, agg1, n);
    // U = tanh(agg1[:, :128] @ W2 + b2)  (conv2);  V = conv4
    sgemm2_kernel<<<g256, 256>>>(agg1, 256, W2, U, n, 128, 256, b2, 0, 1);
    sgemm2_kernel<<<g256, 256>>>(agg1 + 128, 256, W4, V, n, 128, 256, b4, 0, 1);
    // global column max of U -> cvec through W7[0:256]
    cudaMemsetAsync(mv, 0, 256 * sizeof(int));
    colmax_kernel<<<512, 256>>>(U, n, mv);
    cvec_kernel<<<1, 128>>>(mv, W7, cvec);
    // H = V @ W7[256:512] + x @ W7[512:576] + cvec
    sgemm2_kernel<<<g128, 256>>>(V, 256, W7 + 256 * 128, H, n, 256, 128, cvec, 0, 0);
    sgemm2_kernel<<<g128, 256>>>(x, 64, W7 + 512 * 128, H, n, 64, 128, nullptr, 1, 0);
    // out = tanh(P H + b7)
    agg128t_kernel<<<aggBlocks, 256>>>(H, rowptr, csrsrc, csrnorm, dis, b7, out, n);
}

// round 4
// speedup vs baseline: 2.8168x; 2.8168x over previous
#include <cuda_runtime.h>
#include <cuda_bf16.h>
#include <math.h>
#include <stdint.h>

#define MAXN 50000
#define MAXE 400000

// ---------------- static scratch ----------------
__device__ __nv_bfloat16 g_agg0h[MAXN * 64], g_agg0l[MAXN * 64];
__device__ float g_T1[MAXN * 256];
__device__ __nv_bfloat16 g_agg1h[MAXN * 256], g_agg1l[MAXN * 256];
__device__ __nv_bfloat16 g_Vh[MAXN * 320], g_Vl[MAXN * 320];  // V (0:256) | x (256:320)
__device__ float g_H[MAXN * 128];
__device__ float g_dis[MAXN];
__device__ int g_cnt[MAXN], g_rowptr[MAXN + 1], g_cursor[MAXN], g_csrsrc[MAXE];
__device__ float g_csrnorm[MAXE];
__device__ int g_mv[256];
__device__ float g_cvec[128];
__device__ __nv_bfloat16 g_WcTh[256 * 64], g_WcTl[256 * 64];
__device__ __nv_bfloat16 g_W2Th[256 * 128], g_W2Tl[256 * 128];
__device__ __nv_bfloat16 g_W4Th[256 * 128], g_W4Tl[256 * 128];
__device__ __nv_bfloat16 g_W7Th[128 * 320], g_W7Tl[128 * 320];
__device__ float g_bc[256];

// ---------------- helpers ----------------
__device__ __forceinline__ uint32_t smem_u32(const void* p) {
    uint32_t a;
    asm("{ .reg .u64 t; cvta.to.shared.u64 t, %1; cvt.u32.u64 %0, t; }" : "=r"(a) : "l"(p));
    return a;
}
__device__ __forceinline__ void cpasync16(uint32_t dst, const void* src, bool pred) {
    int sz = pred ? 16 : 0;  // src-size 0 => zero-fill
    asm volatile("cp.async.cg.shared.global [%0], [%1], 16, %2;\n" :: "r"(dst), "l"(src), "r"(sz));
}
__device__ __forceinline__ void ldmx4(uint32_t& r0, uint32_t& r1, uint32_t& r2, uint32_t& r3,
                                      uint32_t addr) {
    asm volatile("ldmatrix.sync.aligned.m8n8.x4.shared.b16 {%0,%1,%2,%3}, [%4];"
                 : "=r"(r0), "=r"(r1), "=r"(r2), "=r"(r3) : "r"(addr));
}
__device__ __forceinline__ void mma16816(float* c, const uint32_t* a, const uint32_t* b) {
    asm volatile(
        "mma.sync.aligned.m16n8k16.row.col.f32.bf16.bf16.f32 "
        "{%0,%1,%2,%3}, {%4,%5,%6,%7}, {%8,%9}, {%0,%1,%2,%3};"
        : "+f"(c[0]), "+f"(c[1]), "+f"(c[2]), "+f"(c[3])
        : "r"(a[0]), "r"(a[1]), "r"(a[2]), "r"(a[3]), "r"(b[0]), "r"(b[1]));
}
__device__ __forceinline__ void bsplit(float v, __nv_bfloat16& h, __nv_bfloat16& l) {
    h = __float2bfloat16(v);
    l = __float2bfloat16(v - __bfloat162float(h));
}

// ---------------- CSR build ----------------
__global__ void count_kernel(const int* __restrict__ dst, int e, int* __restrict__ cnt) {
    int i = blockIdx.x * blockDim.x + threadIdx.x;
    if (i < e) atomicAdd(&cnt[dst[i]], 1);
}

__global__ void scan_kernel(const int* __restrict__ cnt, int n, int* __restrict__ rowptr,
                            int* __restrict__ cursor, float* __restrict__ dis) {
    __shared__ int sh[1024];
    int tid = threadIdx.x;
    int run = 0;
    for (int base = 0; base < n; base += 1024) {
        int i = base + tid;
        int v = (i < n) ? cnt[i] : 0;
        sh[tid] = v;
        __syncthreads();
        int val = v;
        for (int off = 1; off < 1024; off <<= 1) {
            int t = (tid >= off) ? sh[tid - off] : 0;
            __syncthreads();
            val += t;
            sh[tid] = val;
            __syncthreads();
        }
        if (i < n) {
            int excl = run + val - v;
            rowptr[i] = excl;
            cursor[i] = excl;
            dis[i] = rsqrtf((float)(v + 1));
        }
        int tot = sh[1023];
        __syncthreads();
        run += tot;
    }
    if (tid == 0) rowptr[n] = run;
}

__global__ void fill_kernel(const int* __restrict__ src, const int* __restrict__ dst, int e,
                            int* __restrict__ cursor, int* __restrict__ csrsrc,
                            float* __restrict__ csrnorm, const float* __restrict__ dis) {
    int i = blockIdx.x * blockDim.x + threadIdx.x;
    if (i >= e) return;
    int d = dst[i], s = src[i];
    int p = atomicAdd(&cursor[d], 1);
    csrsrc[p] = s;
    csrnorm[p] = dis[s] * dis[d];
}

// ---------------- weight conversion (transpose + bf16 hi/lo split) ----------------
__global__ void convw_kernel(const float* __restrict__ W1, const float* __restrict__ W3,
                             const float* __restrict__ W2, const float* __restrict__ W4,
                             const float* __restrict__ W7, const float* __restrict__ b1,
                             const float* __restrict__ b3,
                             __nv_bfloat16* WcTh, __nv_bfloat16* WcTl,
                             __nv_bfloat16* W2Th, __nv_bfloat16* W2Tl,
                             __nv_bfloat16* W4Th, __nv_bfloat16* W4Tl,
                             __nv_bfloat16* W7Th, __nv_bfloat16* W7Tl,
                             float* bc) {
    int i = blockIdx.x * blockDim.x + threadIdx.x;
    if (i < 256) bc[i] = (i < 128) ? b1[i] : b3[i - 128];
    float v;
    __nv_bfloat16 *oh, *ol;
    int off;
    if (i < 16384) {                      // WcT [256][64]
        int c = i >> 6, k = i & 63;
        v = (c < 128) ? W1[k * 128 + c] : W3[k * 128 + (c - 128)];
        oh = WcTh; ol = WcTl; off = i;
    } else if (i < 49152) {               // W2T [256][128]
        int j = i - 16384; int c = j >> 7, k = j & 127;
        v = W2[k * 256 + c]; oh = W2Th; ol = W2Tl; off = j;
    } else if (i < 81920) {               // W4T [256][128]
        int j = i - 49152; int c = j >> 7, k = j & 127;
        v = W4[k * 256 + c]; oh = W4Th; ol = W4Tl; off = j;
    } else if (i < 122880) {              // W7T [128][320]: k<256 -> W7b, k>=256 -> W7c
        int j = i - 81920; int c = j / 320, k = j % 320;
        v = (k < 256) ? W7[(size_t)(256 + k) * 128 + c]
                      : W7[(size_t)(512 + (k - 256)) * 128 + c];
        oh = W7Th; ol = W7Tl; off = j;
    } else return;
    __nv_bfloat16 h, l;
    bsplit(v, h, l);
    oh[off] = h; ol[off] = l;
}

// x -> bf16 hi/lo into cols 256:320 of Vh/Vl (ld=320)
__global__ void convx_kernel(const float* __restrict__ x, __nv_bfloat16* __restrict__ Vh,
                             __nv_bfloat16* __restrict__ Vl, int total) {
    int i = blockIdx.x * blockDim.x + threadIdx.x;
    if (i >= total) return;
    int row = i >> 6, c = i & 63;
    __nv_bfloat16 h, l;
    bsplit(x[i], h, l);
    Vh[(size_t)row * 320 + 256 + c] = h;
    Vl[(size_t)row * 320 + 256 + c] = l;
}

// ---------------- HMMA bf16 GEMM, 3-segment split ----------------
// D[128 x 128] per CTA; A row-major bf16 [n,lda] (hi/lo); Bt row-major [ncol,K] (hi/lo).
// grid = (ceil(n/128), ncol/128). EPI: 0=tanh+bias->C f32
//   1=tanh+bias->column max atomics (mv)   2=tanh+bias->bf16 hi/lo (ldO)
//   3=+addvec->C f32
template <int EPI>
__global__ __launch_bounds__(256)
void hmma_gemm(const __nv_bfloat16* __restrict__ Ahi, const __nv_bfloat16* __restrict__ Alo,
               int lda,
               const __nv_bfloat16* __restrict__ Bhi, const __nv_bfloat16* __restrict__ Blo,
               int K, int n,
               float* __restrict__ C, int ldC,
               const float* __restrict__ addvec,
               __nv_bfloat16* __restrict__ outHi, __nv_bfloat16* __restrict__ outLo, int ldO,
               int* __restrict__ mv) {
    __shared__ __align__(16) __nv_bfloat16 As[2][128 * 40];
    __shared__ __align__(16) __nv_bfloat16 Bs[2][128 * 40];
    int tid = threadIdx.x;
    int lane = tid & 31, warp = tid >> 5;
    int warpM = warp & 1, warpN = warp >> 1;  // 2 x 4
    int rowBase = blockIdx.x * 128;
    int colBase = blockIdx.y * 128;

    float acc[4][4][4];
#pragma unroll
    for (int a = 0; a < 4; a++)
#pragma unroll
        for (int b = 0; b < 4; b++)
#pragma unroll
            for (int c = 0; c < 4; c++) acc[a][b][c] = 0.0f;

    int segsz = K >> 5;  // 32-wide chunks per segment
    int total = 3 * segsz;

    auto loadChunk = [&](int tc, int buf) {
        int seg = tc / segsz, kc = tc % segsz;
        const __nv_bfloat16* Ab = (seg == 1) ? Alo : Ahi;
        const __nv_bfloat16* Bb = (seg == 2) ? Blo : Bhi;
        int k0 = kc << 5;
        uint32_t aB = smem_u32(&As[buf][0]);
        uint32_t bB = smem_u32(&Bs[buf][0]);
#pragma unroll
        for (int i = 0; i < 2; i++) {
            int idx = tid + (i << 8);        // 0..511
            int row = idx >> 2, quad = idx & 3;
            cpasync16(aB + (row * 40 + quad * 8) * 2,
                      Ab + (size_t)(rowBase + row) * lda + k0 + quad * 8,
                      (rowBase + row) < n);
            cpasync16(bB + (row * 40 + quad * 8) * 2,
                      Bb + (size_t)(colBase + row) * K + k0 + quad * 8, true);
        }
        asm volatile("cp.async.commit_group;");
    };

    auto compute = [&](int buf) {
        uint32_t aB = smem_u32(&As[buf][0]);
        uint32_t bB = smem_u32(&Bs[buf][0]);
#pragma unroll
        for (int ks = 0; ks < 2; ks++) {
            uint32_t af[4][4], bf[4][2];
            int arow = warpM * 64 + (lane & 15);
            int acol = ks * 16 + (lane >> 4) * 8;
#pragma unroll
            for (int mi = 0; mi < 4; mi++)
                ldmx4(af[mi][0], af[mi][1], af[mi][2], af[mi][3],
                      aB + ((arow + mi * 16) * 40 + acol) * 2);
#pragma unroll
            for (int np = 0; np < 2; np++) {
                int brow = warpN * 32 + np * 16 + (lane & 7) + ((lane >> 4) << 3);
                int bcol = ks * 16 + (((lane >> 3) & 1) << 3);
                ldmx4(bf[np * 2][0], bf[np * 2][1], bf[np * 2 + 1][0], bf[np * 2 + 1][1],
                      bB + (brow * 40 + bcol) * 2);
            }
#pragma unroll
            for (int mi = 0; mi < 4; mi++)
#pragma unroll
                for (int ni = 0; ni < 4; ni++) mma16816(acc[mi][ni], af[mi], bf[ni]);
        }
    };

    loadChunk(0, 0);
    for (int tc = 0; tc < total; tc++) {
        int buf = tc & 1;
        if (tc + 1 < total) {
            loadChunk(tc + 1, buf ^ 1);
            asm volatile("cp.async.wait_group 1;");
        } else {
            asm volatile("cp.async.wait_group 0;");
        }
        __syncthreads();
        compute(buf);
        __syncthreads();
    }

    // ---------------- epilogue ----------------
    int rBase = rowBase + warpM * 64;
    int cBase = colBase + warpN * 32;
    if (EPI == 1) {
        float cm[8];
#pragma unroll
        for (int j = 0; j < 8; j++) cm[j] = -1e30f;
#pragma unroll
        for (int mi = 0; mi < 4; mi++) {
            int r0 = rBase + mi * 16 + (lane >> 2);
            int r1 = r0 + 8;
#pragma unroll
            for (int ni = 0; ni < 4; ni++) {
                int col = cBase + ni * 8 + (lane & 3) * 2;
                float v0 = (r0 < n) ? tanhf(acc[mi][ni][0] + addvec[col]) : -1e30f;
                float v1 = (r0 < n) ? tanhf(acc[mi][ni][1] + addvec[col + 1]) : -1e30f;
                float v2 = (r1 < n) ? tanhf(acc[mi][ni][2] + addvec[col]) : -1e30f;
                float v3 = (r1 < n) ? tanhf(acc[mi][ni][3] + addvec[col + 1]) : -1e30f;
                cm[ni * 2] = fmaxf(cm[ni * 2], fmaxf(v0, v2));
                cm[ni * 2 + 1] = fmaxf(cm[ni * 2 + 1], fmaxf(v1, v3));
            }
        }
#pragma unroll
        for (int off = 4; off < 32; off <<= 1)
#pragma unroll
            for (int j = 0; j < 8; j++)
                cm[j] = fmaxf(cm[j], __shfl_xor_sync(0xffffffffu, cm[j], off));
        if (lane < 4) {
#pragma unroll
            for (int ni = 0; ni < 4; ni++) {
                int col = cBase + ni * 8 + lane * 2;
                atomicMax(&mv[col], __float_as_int(cm[ni * 2] + 2.0f));
                atomicMax(&mv[col + 1], __float_as_int(cm[ni * 2 + 1] + 2.0f));
            }
        }
    } else {
#pragma unroll
        for (int mi = 0; mi < 4; mi++) {
#pragma unroll
            for (int h = 0; h < 2; h++) {
                int r = rBase + mi * 16 + (lane >> 2) + h * 8;
                if (r >= n) continue;
#pragma unroll
                for (int ni = 0; ni < 4; ni++) {
                    int col = cBase + ni * 8 + (lane & 3) * 2;
                    float v0 = acc[mi][ni][h * 2], v1 = acc[mi][ni][h * 2 + 1];
                    if (EPI == 0) {
                        v0 = tanhf(v0 + addvec[col]);
                        v1 = tanhf(v1 + addvec[col + 1]);
                        *(float2*)(C + (size_t)r * ldC + col) = make_float2(v0, v1);
                    } else if (EPI == 2) {
                        v0 = tanhf(v0 + addvec[col]);
                        v1 = tanhf(v1 + addvec[col + 1]);
                        __nv_bfloat16 h0, l0, h1, l1;
                        bsplit(v0, h0, l0);
                        bsplit(v1, h1, l1);
                        *(__nv_bfloat162*)(outHi + (size_t)r * ldO + col) = __halves2bfloat162(h0, h1);
                        *(__nv_bfloat162*)(outLo + (size_t)r * ldO + col) = __halves2bfloat162(l0, l1);
                    } else {  // EPI == 3
                        v0 += addvec[col];
                        v1 += addvec[col + 1];
                        *(float2*)(C + (size_t)r * ldC + col) = make_float2(v0, v1);
                    }
                }
            }
        }
    }
}

// ---------------- agg F=64 (fp32 in -> bf16 hi/lo out) ----------------
__global__ void agg64_kernel(const float* __restrict__ h, const int* __restrict__ rowptr,
                             const int* __restrict__ csrsrc, const float* __restrict__ csrnorm,
                             const float* __restrict__ dis,
                             __nv_bfloat16* __restrict__ outHi, __nv_bfloat16* __restrict__ outLo,
                             int n) {
    int warp = (blockIdx.x * blockDim.x + threadIdx.x) >> 5;
    int lane = threadIdx.x & 31;
    if (warp >= n) return;
    float2 acc = make_float2(0.f, 0.f);
    int s0 = rowptr[warp], s1 = rowptr[warp + 1];
    int j = s0;
    for (; j + 1 < s1; j += 2) {
        int sa = csrsrc[j], sb = csrsrc[j + 1];
        float wa = csrnorm[j], wb = csrnorm[j + 1];
        float2 va = *(const float2*)(h + (size_t)sa * 64 + lane * 2);
        float2 vb = *(const float2*)(h + (size_t)sb * 64 + lane * 2);
        acc.x += va.x * wa + vb.x * wb;
        acc.y += va.y * wa + vb.y * wb;
    }
    if (j < s1) {
        int s = csrsrc[j];
        float w = csrnorm[j];
        float2 va = *(const float2*)(h + (size_t)s * 64 + lane * 2);
        acc.x += va.x * w;
        acc.y += va.y * w;
    }
    float ds = dis[warp];
    float w2 = ds * ds;
    float2 v = *(const float2*)(h + (size_t)warp * 64 + lane * 2);
    acc.x += v.x * w2;
    acc.y += v.y * w2;
    __nv_bfloat16 h0, l0, h1, l1;
    bsplit(acc.x, h0, l0);
    bsplit(acc.y, h1, l1);
    *(__nv_bfloat162*)(outHi + (size_t)warp * 64 + lane * 2) = __halves2bfloat162(h0, h1);
    *(__nv_bfloat162*)(outLo + (size_t)warp * 64 + lane * 2) = __halves2bfloat162(l0, l1);
}

// ---------------- agg F=256 (fp32 in -> bf16 hi/lo out) ----------------
__global__ void agg256_kernel(const float* __restrict__ h, const int* __restrict__ rowptr,
                              const int* __restrict__ csrsrc, const float* __restrict__ csrnorm,
                              const float* __restrict__ dis,
                              __nv_bfloat16* __restrict__ outHi, __nv_bfloat16* __restrict__ outLo,
                              int n) {
    int warp = (blockIdx.x * blockDim.x + threadIdx.x) >> 5;
    int lane = threadIdx.x & 31;
    if (warp >= n) return;
    float4 a0 = make_float4(0.f, 0.f, 0.f, 0.f), a1 = a0;
    int s0 = rowptr[warp], s1 = rowptr[warp + 1];
    int i0 = lane << 2, i1 = (lane + 32) << 2;
    for (int j = s0; j < s1; j++) {
        int s = csrsrc[j];
        float w = csrnorm[j];
        const float* hp = h + (size_t)s * 256;
        float4 v0 = *(const float4*)(hp + i0);
        float4 v1 = *(const float4*)(hp + i1);
        a0.x += v0.x * w; a0.y += v0.y * w; a0.z += v0.z * w; a0.w += v0.w * w;
        a1.x += v1.x * w; a1.y += v1.y * w; a1.z += v1.z * w; a1.w += v1.w * w;
    }
    float ds = dis[warp];
    float w2 = ds * ds;
    const float* hp = h + (size_t)warp * 256;
    float4 v0 = *(const float4*)(hp + i0);
    float4 v1 = *(const float4*)(hp + i1);
    a0.x += v0.x * w2; a0.y += v0.y * w2; a0.z += v0.z * w2; a0.w += v0.w * w2;
    a1.x += v1.x * w2; a1.y += v1.y * w2; a1.z += v1.z * w2; a1.w += v1.w * w2;
    __nv_bfloat16 h0, l0, h1, l1, h2, l2, h3, l3;
    bsplit(a0.x, h0, l0); bsplit(a0.y, h1, l1); bsplit(a0.z, h2, l2); bsplit(a0.w, h3, l3);
    *(__nv_bfloat162*)(outHi + (size_t)warp * 256 + i0) = __halves2bfloat162(h0, h1);
    *(__nv_bfloat162*)(outHi + (size_t)warp * 256 + i0 + 2) = __halves2bfloat162(h2, h3);
    *(__nv_bfloat162*)(outLo + (size_t)warp * 256 + i0) = __halves2bfloat162(l0, l1);
    *(__nv_bfloat162*)(outLo + (size_t)warp * 256 + i0 + 2) = __halves2bfloat162(l2, l3);
    bsplit(a1.x, h0, l0); bsplit(a1.y, h1, l1); bsplit(a1.z, h2, l2); bsplit(a1.w, h3, l3);
    *(__nv_bfloat162*)(outHi + (size_t)warp * 256 + i1) = __halves2bfloat162(h0, h1);
    *(__nv_bfloat162*)(outHi + (size_t)warp * 256 + i1 + 2) = __halves2bfloat162(h2, h3);
    *(__nv_bfloat162*)(outLo + (size_t)warp * 256 + i1) = __halves2bfloat162(l0, l1);
    *(__nv_bfloat162*)(outLo + (size_t)warp * 256 + i1 + 2) = __halves2bfloat162(l2, l3);
}

// ---------------- agg F=128 + bias + tanh (final, fp32) ----------------
__global__ void agg128t_kernel(const float* __restrict__ h, const int* __restrict__ rowptr,
                               const int* __restrict__ csrsrc, const float* __restrict__ csrnorm,
                               const float* __restrict__ dis, const float* __restrict__ bias,
                               float* __restrict__ out, int n) {
    int warp = (blockIdx.x * blockDim.x + threadIdx.x) >> 5;
    int lane = threadIdx.x & 31;
    if (warp >= n) return;
    float4 acc = make_float4(0.f, 0.f, 0.f, 0.f);
    int s0 = rowptr[warp], s1 = rowptr[warp + 1];
    int idx = lane << 2;
    int j = s0;
    for (; j + 1 < s1; j += 2) {
        int sa = csrsrc[j], sb = csrsrc[j + 1];
        float wa = csrnorm[j], wb = csrnorm[j + 1];
        float4 va = *(const float4*)(h + (size_t)sa * 128 + idx);
        float4 vb = *(const float4*)(h + (size_t)sb * 128 + idx);
        acc.x += va.x * wa + vb.x * wb;
        acc.y += va.y * wa + vb.y * wb;
        acc.z += va.z * wa + vb.z * wb;
        acc.w += va.w * wa + vb.w * wb;
    }
    if (j < s1) {
        int s = csrsrc[j];
        float w = csrnorm[j];
        float4 va = *(const float4*)(h + (size_t)s * 128 + idx);
        acc.x += va.x * w; acc.y += va.y * w; acc.z += va.z * w; acc.w += va.w * w;
    }
    float ds = dis[warp];
    float w2 = ds * ds;
    float4 v = *(const float4*)(h + (size_t)warp * 128 + idx);
    float4 bb = *(const float4*)(bias + idx);
    float4 r;
    r.x = tanhf(acc.x + v.x * w2 + bb.x);
    r.y = tanhf(acc.y + v.y * w2 + bb.y);
    r.z = tanhf(acc.z + v.z * w2 + bb.z);
    r.w = tanhf(acc.w + v.w * w2 + bb.w);
    *(float4*)(out + (size_t)warp * 128 + idx) = r;
}

// ---------------- cvec = (colmax of U) @ W7[0:256,:] ----------------
__global__ void cvec_kernel(const int* __restrict__ mv, const float* __restrict__ W7,
                            float* __restrict__ cvec) {
    int j = threadIdx.x;
    float s = 0.0f;
    for (int k = 0; k < 256; k++)
        s += (__int_as_float(mv[k]) - 2.0f) * W7[(size_t)k * 128 + j];
    cvec[j] = s;
}

extern "C" void kernel_launch(void* const* d_in, const int* in_sizes, int n_in,
                              void* d_out, int out_size) {
    const float* x = (const float*)d_in[0];
    const int* ei = (const int*)d_in[1];
    const float* W1 = (const float*)d_in[3];
    const float* b1 = (const float*)d_in[4];
    const float* W2 = (const float*)d_in[5];
    const float* b2 = (const float*)d_in[6];
    const float* W3 = (const float*)d_in[7];
    const float* b3 = (const float*)d_in[8];
    const float* W4 = (const float*)d_in[9];
    const float* b4 = (const float*)d_in[10];
    const float* W7 = (const float*)d_in[11];
    const float* b7 = (const float*)d_in[12];

    int n = in_sizes[0] / 64;
    int e = in_sizes[1] / 2;
    const int* src = ei;
    const int* dst = ei + e;
    float* out = (float*)d_out;

    __nv_bfloat16 *agg0h, *agg0l, *agg1h, *agg1l, *Vh, *Vl;
    __nv_bfloat16 *WcTh, *WcTl, *W2Th, *W2Tl, *W4Th, *W4Tl, *W7Th, *W7Tl;
    float *T1, *H, *dis, *csrnorm, *cvec, *bc;
    int *cnt, *rowptr, *cursor, *csrsrc, *mv;
    cudaGetSymbolAddress((void**)&agg0h, g_agg0h);
    cudaGetSymbolAddress((void**)&agg0l, g_agg0l);
    cudaGetSymbolAddress((void**)&T1, g_T1);
    cudaGetSymbolAddress((void**)&agg1h, g_agg1h);
    cudaGetSymbolAddress((void**)&agg1l, g_agg1l);
    cudaGetSymbolAddress((void**)&Vh, g_Vh);
    cudaGetSymbolAddress((void**)&Vl, g_Vl);
    cudaGetSymbolAddress((void**)&H, g_H);
    cudaGetSymbolAddress((void**)&dis, g_dis);
    cudaGetSymbolAddress((void**)&cnt, g_cnt);
    cudaGetSymbolAddress((void**)&rowptr, g_rowptr);
    cudaGetSymbolAddress((void**)&cursor, g_cursor);
    cudaGetSymbolAddress((void**)&csrsrc, g_csrsrc);
    cudaGetSymbolAddress((void**)&csrnorm, g_csrnorm);
    cudaGetSymbolAddress((void**)&mv, g_mv);
    cudaGetSymbolAddress((void**)&cvec, g_cvec);
    cudaGetSymbolAddress((void**)&WcTh, g_WcTh);
    cudaGetSymbolAddress((void**)&WcTl, g_WcTl);
    cudaGetSymbolAddress((void**)&W2Th, g_W2Th);
    cudaGetSymbolAddress((void**)&W2Tl, g_W2Tl);
    cudaGetSymbolAddress((void**)&W4Th, g_W4Th);
    cudaGetSymbolAddress((void**)&W4Tl, g_W4Tl);
    cudaGetSymbolAddress((void**)&W7Th, g_W7Th);
    cudaGetSymbolAddress((void**)&W7Tl, g_W7Tl);
    cudaGetSymbolAddress((void**)&bc, g_bc);

    int eb = (e + 255) / 256;
    int aggBlocks = (n + 7) / 8;
    int gm = (n + 127) / 128;
    dim3 g2(gm, 2), g1(gm, 1);

    // CSR build + conversions
    cudaMemsetAsync(cnt, 0, (size_t)n * sizeof(int));
    cudaMemsetAsync(mv, 0, 256 * sizeof(int));
    convw_kernel<<<480, 256>>>(W1, W3, W2, W4, W7, b1, b3, WcTh, WcTl, W2Th, W2Tl,
                               W4Th, W4Tl, W7Th, W7Tl, bc);
    convx_kernel<<<(n * 64 + 255) / 256, 256>>>(x, Vh, Vl, n * 64);
    count_kernel<<<eb, 256>>>(dst, e, cnt);
    scan_kernel<<<1, 1024>>>(cnt, n, rowptr, cursor, dis);
    fill_kernel<<<eb, 256>>>(src, dst, e, cursor, csrsrc, csrnorm, dis);

    // agg0 = P x (shared conv1/conv3), split to bf16
    agg64_kernel<<<aggBlocks, 256>>>(x, rowptr, csrsrc, csrnorm, dis, agg0h, agg0l, n);
    // T1 = tanh(agg0 @ [W1|W3] + [b1|b3])
    hmma_gemm<0><<<g2, 256>>>(agg0h, agg0l, 64, WcTh, WcTl, 64, n,
                              T1, 256, bc, nullptr, nullptr, 0, nullptr);
    // agg1 = P T1, split to bf16
    agg256_kernel<<<aggBlocks, 256>>>(T1, rowptr, csrsrc, csrnorm, dis, agg1h, agg1l, n);
    // colmax( tanh(agg1[:,:128] @ W2 + b2) ) -> mv   (U never stored)
    hmma_gemm<1><<<g2, 256>>>(agg1h, agg1l, 256, W2Th, W2Tl, 128, n,
                              nullptr, 0, b2, nullptr, nullptr, 0, mv);
    // V = tanh(agg1[:,128:] @ W4 + b4) -> bf16 hi/lo into Vh/Vl cols 0:256 (ld=320)
    hmma_gemm<2><<<g2, 256>>>(agg1h + 128, agg1l + 128, 256, W4Th, W4Tl, 128, n,
                              nullptr, 0, b4, Vh, Vl, 320, nullptr);
    // cvec = colmax @ W7[0:256]
    cvec_kernel<<<1, 128>>>(mv, W7, cvec);
    // H = [V | x] @ [W7b; W7c] + cvec   (single K=320 GEMM)
    hmma_gemm<3><<<g1, 256>>>(Vh, Vl, 320, W7Th, W7Tl, 320, n,
                              H, 128, cvec, nullptr, nullptr, 0, nullptr);
    // out = tanh(P H + b7)
    agg128t_kernel<<<aggBlocks, 256>>>(H, rowptr, csrsrc, csrnorm, dis, b7, out, n);
}

// round 5
// speedup vs baseline: 3.4256x; 1.2161x over previous
#include <cuda_runtime.h>
#include <cuda_bf16.h>
#include <math.h>
#include <stdint.h>

#define MAXN 50000
#define MAXE 400000

// ---------------- static scratch ----------------
__device__ __nv_bfloat16 g_agg0h[MAXN * 64], g_agg0l[MAXN * 64];
__device__ float g_T1[MAXN * 256];
__device__ __nv_bfloat16 g_agg1h[MAXN * 256], g_agg1l[MAXN * 256];
__device__ __nv_bfloat16 g_Vh[MAXN * 320], g_Vl[MAXN * 320];  // V (0:256) | x (256:320)
__device__ float g_H[MAXN * 128];
__device__ float g_dis[MAXN];
__device__ int g_cnt[MAXN], g_rowptr[MAXN + 1], g_cursor[MAXN], g_csrsrc[MAXE];
__device__ float g_csrnorm[MAXE];
__device__ int g_bsum[64];
__device__ int g_mv[256];
__device__ float g_cvec[128];
__device__ __nv_bfloat16 g_WcTh[256 * 64], g_WcTl[256 * 64];
__device__ __nv_bfloat16 g_W2Th[256 * 128], g_W2Tl[256 * 128];
__device__ __nv_bfloat16 g_W4Th[256 * 128], g_W4Tl[256 * 128];
__device__ __nv_bfloat16 g_W7Th[128 * 320], g_W7Tl[128 * 320];
__device__ float g_bc[256];

// ---------------- helpers ----------------
__device__ __forceinline__ uint32_t smem_u32(const void* p) {
    uint32_t a;
    asm("{ .reg .u64 t; cvta.to.shared.u64 t, %1; cvt.u32.u64 %0, t; }" : "=r"(a) : "l"(p));
    return a;
}
__device__ __forceinline__ void cpasync16(uint32_t dst, const void* src, bool pred) {
    int sz = pred ? 16 : 0;  // src-size 0 => zero-fill
    asm volatile("cp.async.cg.shared.global [%0], [%1], 16, %2;\n" :: "r"(dst), "l"(src), "r"(sz));
}
__device__ __forceinline__ void ldmx4(uint32_t& r0, uint32_t& r1, uint32_t& r2, uint32_t& r3,
                                      uint32_t addr) {
    asm volatile("ldmatrix.sync.aligned.m8n8.x4.shared.b16 {%0,%1,%2,%3}, [%4];"
                 : "=r"(r0), "=r"(r1), "=r"(r2), "=r"(r3) : "r"(addr));
}
__device__ __forceinline__ void mma16816(float* c, const uint32_t* a, const uint32_t* b) {
    asm volatile(
        "mma.sync.aligned.m16n8k16.row.col.f32.bf16.bf16.f32 "
        "{%0,%1,%2,%3}, {%4,%5,%6,%7}, {%8,%9}, {%0,%1,%2,%3};"
        : "+f"(c[0]), "+f"(c[1]), "+f"(c[2]), "+f"(c[3])
        : "r"(a[0]), "r"(a[1]), "r"(a[2]), "r"(a[3]), "r"(b[0]), "r"(b[1]));
}
__device__ __forceinline__ void bsplit(float v, __nv_bfloat16& h, __nv_bfloat16& l) {
    h = __float2bfloat16(v);
    l = __float2bfloat16(v - __bfloat162float(h));
}

// ---------------- CSR build ----------------
__global__ void count_kernel(const int* __restrict__ dst, int e, int* __restrict__ cnt) {
    int i = blockIdx.x * blockDim.x + threadIdx.x;
    if (i < e) atomicAdd(&cnt[dst[i]], 1);
}

// --- multi-block scan: phase 1 (per-block sums; block = 256 thr x 16 elems) ---
__global__ void scan1_kernel(const int* __restrict__ cnt, int n, int* __restrict__ bsum) {
    int tid = threadIdx.x;
    int base = (blockIdx.x * 256 + tid) * 16;
    int s = 0;
#pragma unroll
    for (int i = 0; i < 16; i++) {
        int idx = base + i;
        if (idx < n) s += cnt[idx];
    }
    __shared__ int sh[8];
#pragma unroll
    for (int o = 16; o; o >>= 1) s += __shfl_down_sync(0xffffffffu, s, o);
    if ((tid & 31) == 0) sh[tid >> 5] = s;
    __syncthreads();
    if (tid < 8) {
        int v = sh[tid];
#pragma unroll
        for (int o = 4; o; o >>= 1) v += __shfl_down_sync(0xffu, v, o);
        if (tid == 0) bsum[blockIdx.x] = v;
    }
}

// --- phase 2: single-warp exclusive scan of block sums (nb <= 32) ---
__global__ void scan2_kernel(int* __restrict__ bsum, int nb, int* __restrict__ rowptr, int n) {
    int tid = threadIdx.x;  // 32 threads
    int v = (tid < nb) ? bsum[tid] : 0;
    int orig = v;
#pragma unroll
    for (int o = 1; o < 32; o <<= 1) {
        int t = __shfl_up_sync(0xffffffffu, v, o);
        if (tid >= o) v += t;
    }
    if (tid < nb) bsum[tid] = v - orig;
    if (tid == 31) rowptr[n] = v;
}

// --- phase 3: per-element exclusive prefix + cursor + dis ---
__global__ void scan3_kernel(const int* __restrict__ cnt, int n, const int* __restrict__ bsum,
                             int* __restrict__ rowptr, int* __restrict__ cursor,
                             float* __restrict__ dis) {
    int tid = threadIdx.x;
    int lane = tid & 31, warp = tid >> 5;
    int base = (blockIdx.x * 256 + tid) * 16;
    int vals[16];
    int s = 0;
#pragma unroll
    for (int i = 0; i < 16; i++) {
        int idx = base + i;
        vals[i] = (idx < n) ? cnt[idx] : 0;
        s += vals[i];
    }
    int incl = s;
#pragma unroll
    for (int o = 1; o < 32; o <<= 1) {
        int t = __shfl_up_sync(0xffffffffu, incl, o);
        if (lane >= o) incl += t;
    }
    __shared__ int wsum[8];
    if (lane == 31) wsum[warp] = incl;
    __syncthreads();
    int woff = 0;
    for (int w = 0; w < warp; w++) woff += wsum[w];
    int excl = bsum[blockIdx.x] + woff + (incl - s);
#pragma unroll
    for (int i = 0; i < 16; i++) {
        int idx = base + i;
        if (idx < n) {
            rowptr[idx] = excl;
            cursor[idx] = excl;
            dis[idx] = rsqrtf((float)(vals[i] + 1));
            excl += vals[i];
        }
    }
}

__global__ void fill_kernel(const int* __restrict__ src, const int* __restrict__ dst, int e,
                            int* __restrict__ cursor, int* __restrict__ csrsrc,
                            float* __restrict__ csrnorm, const float* __restrict__ dis) {
    int i = blockIdx.x * blockDim.x + threadIdx.x;
    if (i >= e) return;
    int d = dst[i], s = src[i];
    int p = atomicAdd(&cursor[d], 1);
    csrsrc[p] = s;
    csrnorm[p] = dis[s] * dis[d];
}

// ---------------- weight conversion (transpose + bf16 hi/lo split) ----------------
__global__ void convw_kernel(const float* __restrict__ W1, const float* __restrict__ W3,
                             const float* __restrict__ W2, const float* __restrict__ W4,
                             const float* __restrict__ W7, const float* __restrict__ b1,
                             const float* __restrict__ b3,
                             __nv_bfloat16* WcTh, __nv_bfloat16* WcTl,
                             __nv_bfloat16* W2Th, __nv_bfloat16* W2Tl,
                             __nv_bfloat16* W4Th, __nv_bfloat16* W4Tl,
                             __nv_bfloat16* W7Th, __nv_bfloat16* W7Tl,
                             float* bc) {
    int i = blockIdx.x * blockDim.x + threadIdx.x;
    if (i < 256) bc[i] = (i < 128) ? b1[i] : b3[i - 128];
    float v;
    __nv_bfloat16 *oh, *ol;
    int off;
    if (i < 16384) {                      // WcT [256][64]
        int c = i >> 6, k = i & 63;
        v = (c < 128) ? W1[k * 128 + c] : W3[k * 128 + (c - 128)];
        oh = WcTh; ol = WcTl; off = i;
    } else if (i < 49152) {               // W2T [256][128]
        int j = i - 16384; int c = j >> 7, k = j & 127;
        v = W2[k * 256 + c]; oh = W2Th; ol = W2Tl; off = j;
    } else if (i < 81920) {               // W4T [256][128]
        int j = i - 49152; int c = j >> 7, k = j & 127;
        v = W4[k * 256 + c]; oh = W4Th; ol = W4Tl; off = j;
    } else if (i < 122880) {              // W7T [128][320]
        int j = i - 81920; int c = j / 320, k = j % 320;
        v = (k < 256) ? W7[(size_t)(256 + k) * 128 + c]
                      : W7[(size_t)(512 + (k - 256)) * 128 + c];
        oh = W7Th; ol = W7Tl; off = j;
    } else return;
    __nv_bfloat16 h, l;
    bsplit(v, h, l);
    oh[off] = h; ol[off] = l;
}

// x -> bf16 hi/lo into cols 256:320 of Vh/Vl (ld=320)
__global__ void convx_kernel(const float* __restrict__ x, __nv_bfloat16* __restrict__ Vh,
                             __nv_bfloat16* __restrict__ Vl, int total) {
    int i = blockIdx.x * blockDim.x + threadIdx.x;
    if (i >= total) return;
    int row = i >> 6, c = i & 63;
    __nv_bfloat16 h, l;
    bsplit(x[i], h, l);
    Vh[(size_t)row * 320 + 256 + c] = h;
    Vl[(size_t)row * 320 + 256 + c] = l;
}

// ---------------- shared HMMA mainloop (3-segment bf16 split) ----------------
__device__ __forceinline__ void gemm_mainloop(
    const __nv_bfloat16* __restrict__ Ahi, const __nv_bfloat16* __restrict__ Alo, int lda,
    const __nv_bfloat16* __restrict__ Bhi, const __nv_bfloat16* __restrict__ Blo,
    int K, int n, int rowBase, int colBase,
    __nv_bfloat16 (*As)[128 * 40], __nv_bfloat16 (*Bs)[128 * 40],
    float acc[4][4][4]) {
    int tid = threadIdx.x;
    int lane = tid & 31, warp = tid >> 5;
    int warpM = warp & 1, warpN = warp >> 1;

    int segsz = K >> 5;
    int total = 3 * segsz;

    auto loadChunk = [&](int tc, int buf) {
        int seg = tc / segsz, kc = tc % segsz;
        const __nv_bfloat16* Ab = (seg == 1) ? Alo : Ahi;
        const __nv_bfloat16* Bb = (seg == 2) ? Blo : Bhi;
        int k0 = kc << 5;
        uint32_t aB = smem_u32(&As[buf][0]);
        uint32_t bB = smem_u32(&Bs[buf][0]);
#pragma unroll
        for (int i = 0; i < 2; i++) {
            int idx = tid + (i << 8);
            int row = idx >> 2, quad = idx & 3;
            cpasync16(aB + (row * 40 + quad * 8) * 2,
                      Ab + (size_t)(rowBase + row) * lda + k0 + quad * 8,
                      (rowBase + row) < n);
            cpasync16(bB + (row * 40 + quad * 8) * 2,
                      Bb + (size_t)(colBase + row) * K + k0 + quad * 8, true);
        }
        asm volatile("cp.async.commit_group;");
    };

    auto compute = [&](int buf) {
        uint32_t aB = smem_u32(&As[buf][0]);
        uint32_t bB = smem_u32(&Bs[buf][0]);
#pragma unroll
        for (int ks = 0; ks < 2; ks++) {
            uint32_t af[4][4], bf[4][2];
            int arow = warpM * 64 + (lane & 15);
            int acol = ks * 16 + (lane >> 4) * 8;
#pragma unroll
            for (int mi = 0; mi < 4; mi++)
                ldmx4(af[mi][0], af[mi][1], af[mi][2], af[mi][3],
                      aB + ((arow + mi * 16) * 40 + acol) * 2);
#pragma unroll
            for (int np = 0; np < 2; np++) {
                int brow = warpN * 32 + np * 16 + (lane & 7) + ((lane >> 4) << 3);
                int bcol = ks * 16 + (((lane >> 3) & 1) << 3);
                ldmx4(bf[np * 2][0], bf[np * 2][1], bf[np * 2 + 1][0], bf[np * 2 + 1][1],
                      bB + (brow * 40 + bcol) * 2);
            }
#pragma unroll
            for (int mi = 0; mi < 4; mi++)
#pragma unroll
                for (int ni = 0; ni < 4; ni++) mma16816(acc[mi][ni], af[mi], bf[ni]);
        }
    };

    loadChunk(0, 0);
    for (int tc = 0; tc < total; tc++) {
        int buf = tc & 1;
        if (tc + 1 < total) {
            loadChunk(tc + 1, buf ^ 1);
            asm volatile("cp.async.wait_group 1;");
        } else {
            asm volatile("cp.async.wait_group 0;");
        }
        __syncthreads();
        compute(buf);
        __syncthreads();
    }
}

// ---------------- epilogue device functions ----------------
__device__ __forceinline__ void epi_colmax(float acc[4][4][4], int n, int rBase, int cBase,
                                           int lane, const float* __restrict__ addvec,
                                           int* __restrict__ mv) {
    float cm[8];
#pragma unroll
    for (int j = 0; j < 8; j++) cm[j] = -1e30f;
#pragma unroll
    for (int mi = 0; mi < 4; mi++) {
        int r0 = rBase + mi * 16 + (lane >> 2);
        int r1 = r0 + 8;
#pragma unroll
        for (int ni = 0; ni < 4; ni++) {
            int col = cBase + ni * 8 + (lane & 3) * 2;
            float v0 = (r0 < n) ? tanhf(acc[mi][ni][0] + addvec[col]) : -1e30f;
            float v1 = (r0 < n) ? tanhf(acc[mi][ni][1] + addvec[col + 1]) : -1e30f;
            float v2 = (r1 < n) ? tanhf(acc[mi][ni][2] + addvec[col]) : -1e30f;
            float v3 = (r1 < n) ? tanhf(acc[mi][ni][3] + addvec[col + 1]) : -1e30f;
            cm[ni * 2] = fmaxf(cm[ni * 2], fmaxf(v0, v2));
            cm[ni * 2 + 1] = fmaxf(cm[ni * 2 + 1], fmaxf(v1, v3));
        }
    }
#pragma unroll
    for (int off = 4; off < 32; off <<= 1)
#pragma unroll
        for (int j = 0; j < 8; j++)
            cm[j] = fmaxf(cm[j], __shfl_xor_sync(0xffffffffu, cm[j], off));
    if (lane < 4) {
#pragma unroll
        for (int ni = 0; ni < 4; ni++) {
            int col = cBase + ni * 8 + lane * 2;
            atomicMax(&mv[col], __float_as_int(cm[ni * 2] + 2.0f));
            atomicMax(&mv[col + 1], __float_as_int(cm[ni * 2 + 1] + 2.0f));
        }
    }
}

// mode 0: tanh+bias -> C f32 | mode 2: tanh+bias -> bf16 hi/lo | mode 3: +addvec -> C f32
template <int MODE>
__device__ __forceinline__ void epi_store(float acc[4][4][4], int n, int rBase, int cBase,
                                          int lane, const float* __restrict__ addvec,
                                          float* __restrict__ C, int ldC,
                                          __nv_bfloat16* __restrict__ outHi,
                                          __nv_bfloat16* __restrict__ outLo, int ldO) {
#pragma unroll
    for (int mi = 0; mi < 4; mi++) {
#pragma unroll
        for (int h = 0; h < 2; h++) {
            int r = rBase + mi * 16 + (lane >> 2) + h * 8;
            if (r >= n) continue;
#pragma unroll
            for (int ni = 0; ni < 4; ni++) {
                int col = cBase + ni * 8 + (lane & 3) * 2;
                float v0 = acc[mi][ni][h * 2], v1 = acc[mi][ni][h * 2 + 1];
                if (MODE == 0) {
                    v0 = tanhf(v0 + addvec[col]);
                    v1 = tanhf(v1 + addvec[col + 1]);
                    *(float2*)(C + (size_t)r * ldC + col) = make_float2(v0, v1);
                } else if (MODE == 2) {
                    v0 = tanhf(v0 + addvec[col]);
                    v1 = tanhf(v1 + addvec[col + 1]);
                    __nv_bfloat16 h0, l0, h1, l1;
                    bsplit(v0, h0, l0);
                    bsplit(v1, h1, l1);
                    *(__nv_bfloat162*)(outHi + (size_t)r * ldO + col) = __halves2bfloat162(h0, h1);
                    *(__nv_bfloat162*)(outLo + (size_t)r * ldO + col) = __halves2bfloat162(l0, l1);
                } else {
                    v0 += addvec[col];
                    v1 += addvec[col + 1];
                    *(float2*)(C + (size_t)r * ldC + col) = make_float2(v0, v1);
                }
            }
        }
    }
}

// ---------------- standalone GEMMs (EPI 0 / 3) ----------------
template <int MODE>
__global__ __launch_bounds__(256)
void hmma_gemm(const __nv_bfloat16* __restrict__ Ahi, const __nv_bfloat16* __restrict__ Alo,
               int lda,
               const __nv_bfloat16* __restrict__ Bhi, const __nv_bfloat16* __restrict__ Blo,
               int K, int n, float* __restrict__ C, int ldC,
               const float* __restrict__ addvec) {
    __shared__ __align__(16) __nv_bfloat16 As[2][128 * 40];
    __shared__ __align__(16) __nv_bfloat16 Bs[2][128 * 40];
    float acc[4][4][4];
#pragma unroll
    for (int a = 0; a < 4; a++)
#pragma unroll
        for (int b = 0; b < 4; b++)
#pragma unroll
            for (int c = 0; c < 4; c++) acc[a][b][c] = 0.0f;
    int rowBase = blockIdx.x * 128, colBase = blockIdx.y * 128;
    gemm_mainloop(Ahi, Alo, lda, Bhi, Blo, K, n, rowBase, colBase, As, Bs, acc);
    int lane = threadIdx.x & 31, warp = threadIdx.x >> 5;
    int rBase = rowBase + (warp & 1) * 64, cBase = colBase + (warp >> 1) * 32;
    epi_store<MODE>(acc, n, rBase, cBase, lane, addvec, C, ldC, nullptr, nullptr, 0);
}

// ---------------- merged U/V GEMM (z=0: colmax; z=1: V -> bf16 split) ----------------
__global__ __launch_bounds__(256)
void hmma_gemm_uv(const __nv_bfloat16* __restrict__ agg1h,
                  const __nv_bfloat16* __restrict__ agg1l,
                  const __nv_bfloat16* __restrict__ W2Th, const __nv_bfloat16* __restrict__ W2Tl,
                  const __nv_bfloat16* __restrict__ W4Th, const __nv_bfloat16* __restrict__ W4Tl,
                  int n, const float* __restrict__ b2, const float* __restrict__ b4,
                  __nv_bfloat16* __restrict__ Vh, __nv_bfloat16* __restrict__ Vl,
                  int* __restrict__ mv) {
    __shared__ __align__(16) __nv_bfloat16 As[2][128 * 40];
    __shared__ __align__(16) __nv_bfloat16 Bs[2][128 * 40];
    float acc[4][4][4];
#pragma unroll
    for (int a = 0; a < 4; a++)
#pragma unroll
        for (int b = 0; b < 4; b++)
#pragma unroll
            for (int c = 0; c < 4; c++) acc[a][b][c] = 0.0f;
    int z = blockIdx.z;
    const __nv_bfloat16* Ahi = agg1h + (z ? 128 : 0);
    const __nv_bfloat16* Alo = agg1l + (z ? 128 : 0);
    const __nv_bfloat16* Bhi = z ? W4Th : W2Th;
    const __nv_bfloat16* Blo = z ? W4Tl : W2Tl;
    int rowBase = blockIdx.x * 128, colBase = blockIdx.y * 128;
    gemm_mainloop(Ahi, Alo, 256, Bhi, Blo, 128, n, rowBase, colBase, As, Bs, acc);
    int lane = threadIdx.x & 31, warp = threadIdx.x >> 5;
    int rBase = rowBase + (warp & 1) * 64, cBase = colBase + (warp >> 1) * 32;
    if (z == 0) {
        epi_colmax(acc, n, rBase, cBase, lane, b2, mv);
    } else {
        epi_store<2>(acc, n, rBase, cBase, lane, b4, nullptr, 0, Vh, Vl, 320);
    }
}

// ---------------- agg F=64 (fp32 in -> bf16 hi/lo out) ----------------
__global__ void agg64_kernel(const float* __restrict__ h, const int* __restrict__ rowptr,
                             const int* __restrict__ csrsrc, const float* __restrict__ csrnorm,
                             const float* __restrict__ dis,
                             __nv_bfloat16* __restrict__ outHi, __nv_bfloat16* __restrict__ outLo,
                             int n) {
    int warp = (blockIdx.x * blockDim.x + threadIdx.x) >> 5;
    int lane = threadIdx.x & 31;
    if (warp >= n) return;
    float2 acc = make_float2(0.f, 0.f);
    int s0 = rowptr[warp], s1 = rowptr[warp + 1];
    int j = s0;
    for (; j + 1 < s1; j += 2) {
        int sa = csrsrc[j], sb = csrsrc[j + 1];
        float wa = csrnorm[j], wb = csrnorm[j + 1];
        float2 va = *(const float2*)(h + (size_t)sa * 64 + lane * 2);
        float2 vb = *(const float2*)(h + (size_t)sb * 64 + lane * 2);
        acc.x += va.x * wa + vb.x * wb;
        acc.y += va.y * wa + vb.y * wb;
    }
    if (j < s1) {
        int s = csrsrc[j];
        float w = csrnorm[j];
        float2 va = *(const float2*)(h + (size_t)s * 64 + lane * 2);
        acc.x += va.x * w;
        acc.y += va.y * w;
    }
    float ds = dis[warp];
    float w2 = ds * ds;
    float2 v = *(const float2*)(h + (size_t)warp * 64 + lane * 2);
    acc.x += v.x * w2;
    acc.y += v.y * w2;
    __nv_bfloat16 h0, l0, h1, l1;
    bsplit(acc.x, h0, l0);
    bsplit(acc.y, h1, l1);
    *(__nv_bfloat162*)(outHi + (size_t)warp * 64 + lane * 2) = __halves2bfloat162(h0, h1);
    *(__nv_bfloat162*)(outLo + (size_t)warp * 64 + lane * 2) = __halves2bfloat162(l0, l1);
}

// ---------------- agg F=256 (fp32 in -> bf16 hi/lo out) ----------------
__global__ void agg256_kernel(const float* __restrict__ h, const int* __restrict__ rowptr,
                              const int* __restrict__ csrsrc, const float* __restrict__ csrnorm,
                              const float* __restrict__ dis,
                              __nv_bfloat16* __restrict__ outHi, __nv_bfloat16* __restrict__ outLo,
                              int n) {
    int warp = (blockIdx.x * blockDim.x + threadIdx.x) >> 5;
    int lane = threadIdx.x & 31;
    if (warp >= n) return;
    float4 a0 = make_float4(0.f, 0.f, 0.f, 0.f), a1 = a0;
    int s0 = rowptr[warp], s1 = rowptr[warp + 1];
    int i0 = lane << 2, i1 = (lane + 32) << 2;
    for (int j = s0; j < s1; j++) {
        int s = csrsrc[j];
        float w = csrnorm[j];
        const float* hp = h + (size_t)s * 256;
        float4 v0 = *(const float4*)(hp + i0);
        float4 v1 = *(const float4*)(hp + i1);
        a0.x += v0.x * w; a0.y += v0.y * w; a0.z += v0.z * w; a0.w += v0.w * w;
        a1.x += v1.x * w; a1.y += v1.y * w; a1.z += v1.z * w; a1.w += v1.w * w;
    }
    float ds = dis[warp];
    float w2 = ds * ds;
    const float* hp = h + (size_t)warp * 256;
    float4 v0 = *(const float4*)(hp + i0);
    float4 v1 = *(const float4*)(hp + i1);
    a0.x += v0.x * w2; a0.y += v0.y * w2; a0.z += v0.z * w2; a0.w += v0.w * w2;
    a1.x += v1.x * w2; a1.y += v1.y * w2; a1.z += v1.z * w2; a1.w += v1.w * w2;
    __nv_bfloat16 h0, l0, h1, l1, h2, l2, h3, l3;
    bsplit(a0.x, h0, l0); bsplit(a0.y, h1, l1); bsplit(a0.z, h2, l2); bsplit(a0.w, h3, l3);
    *(__nv_bfloat162*)(outHi + (size_t)warp * 256 + i0) = __halves2bfloat162(h0, h1);
    *(__nv_bfloat162*)(outHi + (size_t)warp * 256 + i0 + 2) = __halves2bfloat162(h2, h3);
    *(__nv_bfloat162*)(outLo + (size_t)warp * 256 + i0) = __halves2bfloat162(l0, l1);
    *(__nv_bfloat162*)(outLo + (size_t)warp * 256 + i0 + 2) = __halves2bfloat162(l2, l3);
    bsplit(a1.x, h0, l0); bsplit(a1.y, h1, l1); bsplit(a1.z, h2, l2); bsplit(a1.w, h3, l3);
    *(__nv_bfloat162*)(outHi + (size_t)warp * 256 + i1) = __halves2bfloat162(h0, h1);
    *(__nv_bfloat162*)(outHi + (size_t)warp * 256 + i1 + 2) = __halves2bfloat162(h2, h3);
    *(__nv_bfloat162*)(outLo + (size_t)warp * 256 + i1) = __halves2bfloat162(l0, l1);
    *(__nv_bfloat162*)(outLo + (size_t)warp * 256 + i1 + 2) = __halves2bfloat162(l2, l3);
}

// ---------------- agg F=128 + bias + tanh (final, fp32) ----------------
__global__ void agg128t_kernel(const float* __restrict__ h, const int* __restrict__ rowptr,
                               const int* __restrict__ csrsrc, const float* __restrict__ csrnorm,
                               const float* __restrict__ dis, const float* __restrict__ bias,
                               float* __restrict__ out, int n) {
    int warp = (blockIdx.x * blockDim.x + threadIdx.x) >> 5;
    int lane = threadIdx.x & 31;
    if (warp >= n) return;
    float4 acc = make_float4(0.f, 0.f, 0.f, 0.f);
    int s0 = rowptr[warp], s1 = rowptr[warp + 1];
    int idx = lane << 2;
    int j = s0;
    for (; j + 1 < s1; j += 2) {
        int sa = csrsrc[j], sb = csrsrc[j + 1];
        float wa = csrnorm[j], wb = csrnorm[j + 1];
        float4 va = *(const float4*)(h + (size_t)sa * 128 + idx);
        float4 vb = *(const float4*)(h + (size_t)sb * 128 + idx);
        acc.x += va.x * wa + vb.x * wb;
        acc.y += va.y * wa + vb.y * wb;
        acc.z += va.z * wa + vb.z * wb;
        acc.w += va.w * wa + vb.w * wb;
    }
    if (j < s1) {
        int s = csrsrc[j];
        float w = csrnorm[j];
        float4 va = *(const float4*)(h + (size_t)s * 128 + idx);
        acc.x += va.x * w; acc.y += va.y * w; acc.z += va.z * w; acc.w += va.w * w;
    }
    float ds = dis[warp];
    float w2 = ds * ds;
    float4 v = *(const float4*)(h + (size_t)warp * 128 + idx);
    float4 bb = *(const float4*)(bias + idx);
    float4 r;
    r.x = tanhf(acc.x + v.x * w2 + bb.x);
    r.y = tanhf(acc.y + v.y * w2 + bb.y);
    r.z = tanhf(acc.z + v.z * w2 + bb.z);
    r.w = tanhf(acc.w + v.w * w2 + bb.w);
    *(float4*)(out + (size_t)warp * 128 + idx) = r;
}

// ---------------- cvec = (colmax of U) @ W7[0:256,:] ----------------
__global__ void cvec_kernel(const int* __restrict__ mv, const float* __restrict__ W7,
                            float* __restrict__ cvec) {
    int j = threadIdx.x;
    float s = 0.0f;
    for (int k = 0; k < 256; k++)
        s += (__int_as_float(mv[k]) - 2.0f) * W7[(size_t)k * 128 + j];
    cvec[j] = s;
}

extern "C" void kernel_launch(void* const* d_in, const int* in_sizes, int n_in,
                              void* d_out, int out_size) {
    const float* x = (const float*)d_in[0];
    const int* ei = (const int*)d_in[1];
    const float* W1 = (const float*)d_in[3];
    const float* b1 = (const float*)d_in[4];
    const float* W2 = (const float*)d_in[5];
    const float* b2 = (const float*)d_in[6];
    const float* W3 = (const float*)d_in[7];
    const float* b3 = (const float*)d_in[8];
    const float* W4 = (const float*)d_in[9];
    const float* b4 = (const float*)d_in[10];
    const float* W7 = (const float*)d_in[11];
    const float* b7 = (const float*)d_in[12];

    int n = in_sizes[0] / 64;
    int e = in_sizes[1] / 2;
    const int* src = ei;
    const int* dst = ei + e;
    float* out = (float*)d_out;

    __nv_bfloat16 *agg0h, *agg0l, *agg1h, *agg1l, *Vh, *Vl;
    __nv_bfloat16 *WcTh, *WcTl, *W2Th, *W2Tl, *W4Th, *W4Tl, *W7Th, *W7Tl;
    float *T1, *H, *dis, *csrnorm, *cvec, *bc;
    int *cnt, *rowptr, *cursor, *csrsrc, *mv, *bsum;
    cudaGetSymbolAddress((void**)&agg0h, g_agg0h);
    cudaGetSymbolAddress((void**)&agg0l, g_agg0l);
    cudaGetSymbolAddress((void**)&T1, g_T1);
    cudaGetSymbolAddress((void**)&agg1h, g_agg1h);
    cudaGetSymbolAddress((void**)&agg1l, g_agg1l);
    cudaGetSymbolAddress((void**)&Vh, g_Vh);
    cudaGetSymbolAddress((void**)&Vl, g_Vl);
    cudaGetSymbolAddress((void**)&H, g_H);
    cudaGetSymbolAddress((void**)&dis, g_dis);
    cudaGetSymbolAddress((void**)&cnt, g_cnt);
    cudaGetSymbolAddress((void**)&rowptr, g_rowptr);
    cudaGetSymbolAddress((void**)&cursor, g_cursor);
    cudaGetSymbolAddress((void**)&csrsrc, g_csrsrc);
    cudaGetSymbolAddress((void**)&csrnorm, g_csrnorm);
    cudaGetSymbolAddress((void**)&bsum, g_bsum);
    cudaGetSymbolAddress((void**)&mv, g_mv);
    cudaGetSymbolAddress((void**)&cvec, g_cvec);
    cudaGetSymbolAddress((void**)&WcTh, g_WcTh);
    cudaGetSymbolAddress((void**)&WcTl, g_WcTl);
    cudaGetSymbolAddress((void**)&W2Th, g_W2Th);
    cudaGetSymbolAddress((void**)&W2Tl, g_W2Tl);
    cudaGetSymbolAddress((void**)&W4Th, g_W4Th);
    cudaGetSymbolAddress((void**)&W4Tl, g_W4Tl);
    cudaGetSymbolAddress((void**)&W7Th, g_W7Th);
    cudaGetSymbolAddress((void**)&W7Tl, g_W7Tl);
    cudaGetSymbolAddress((void**)&bc, g_bc);

    int eb = (e + 255) / 256;
    int aggBlocks = (n + 7) / 8;
    int gm = (n + 127) / 128;
    int nb = (n + 4095) / 4096;
    dim3 g2(gm, 2), g1(gm, 1), guv(gm, 2, 2);

    // CSR build + conversions
    cudaMemsetAsync(cnt, 0, (size_t)n * sizeof(int));
    cudaMemsetAsync(mv, 0, 256 * sizeof(int));
    convw_kernel<<<480, 256>>>(W1, W3, W2, W4, W7, b1, b3, WcTh, WcTl, W2Th, W2Tl,
                               W4Th, W4Tl, W7Th, W7Tl, bc);
    convx_kernel<<<(n * 64 + 255) / 256, 256>>>(x, Vh, Vl, n * 64);
    count_kernel<<<eb, 256>>>(dst, e, cnt);
    scan1_kernel<<<nb, 256>>>(cnt, n, bsum);
    scan2_kernel<<<1, 32>>>(bsum, nb, rowptr, n);
    scan3_kernel<<<nb, 256>>>(cnt, n, bsum, rowptr, cursor, dis);
    fill_kernel<<<eb, 256>>>(src, dst, e, cursor, csrsrc, csrnorm, dis);

    // agg0 = P x (shared conv1/conv3), split to bf16
    agg64_kernel<<<aggBlocks, 256>>>(x, rowptr, csrsrc, csrnorm, dis, agg0h, agg0l, n);
    // T1 = tanh(agg0 @ [W1|W3] + [b1|b3])
    hmma_gemm<0><<<g2, 256>>>(agg0h, agg0l, 64, WcTh, WcTl, 64, n, T1, 256, bc);
    // agg1 = P T1, split to bf16
    agg256_kernel<<<aggBlocks, 256>>>(T1, rowptr, csrsrc, csrnorm, dis, agg1h, agg1l, n);
    // merged: z=0 colmax(tanh(agg1[:,:128]@W2+b2)) -> mv; z=1 V=tanh(agg1[:,128:]@W4+b4)
    hmma_gemm_uv<<<guv, 256>>>(agg1h, agg1l, W2Th, W2Tl, W4Th, W4Tl, n, b2, b4, Vh, Vl, mv);
    // cvec = colmax @ W7[0:256]
    cvec_kernel<<<1, 128>>>(mv, W7, cvec);
    // H = [V | x] @ [W7b; W7c] + cvec   (single K=320 GEMM)
    hmma_gemm<3><<<g1, 256>>>(Vh, Vl, 320, W7Th, W7Tl, 320, n, H, 128, cvec);
    // out = tanh(P H + b7)
    agg128t_kernel<<<aggBlocks, 256>>>(H, rowptr, csrsrc, csrnorm, dis, b7, out, n);
}

// round 6
// speedup vs baseline: 3.9414x; 1.1506x over previous
#include <cuda_runtime.h>
#include <cuda_fp16.h>
#include <math.h>
#include <stdint.h>

#define MAXN 50000
#define MAXE 400000

// ---------------- static scratch ----------------
__device__ __half g_agg0h[MAXN * 64], g_agg0l[MAXN * 64];
__device__ float g_T1[MAXN * 256];
__device__ __half g_agg1h[MAXN * 256], g_agg1l[MAXN * 256];
__device__ __half g_Vh[MAXN * 320], g_Vl[MAXN * 320];  // V (0:256) | x (256:320)
__device__ float g_H[MAXN * 128];
__device__ float g_dis[MAXN];
__device__ int g_cnt[MAXN], g_rowptr[MAXN + 1], g_cursor[MAXN], g_csrsrc[MAXE];
__device__ float g_csrnorm[MAXE];
__device__ int g_bsum[64];
__device__ int g_mv[256];
__device__ float g_cvec[128];
__device__ __half g_WcT[256 * 64];
__device__ __half g_W2T[256 * 128];
__device__ __half g_W4T[256 * 128];
__device__ __half g_W7T[128 * 320];
__device__ float g_bc[256];

// ---------------- helpers ----------------
__device__ __forceinline__ uint32_t smem_u32(const void* p) {
    uint32_t a;
    asm("{ .reg .u64 t; cvta.to.shared.u64 t, %1; cvt.u32.u64 %0, t; }" : "=r"(a) : "l"(p));
    return a;
}
__device__ __forceinline__ void cpasync16(uint32_t dst, const void* src, bool pred) {
    int sz = pred ? 16 : 0;  // src-size 0 => zero-fill
    asm volatile("cp.async.cg.shared.global [%0], [%1], 16, %2;\n" :: "r"(dst), "l"(src), "r"(sz));
}
__device__ __forceinline__ void ldmx4(uint32_t& r0, uint32_t& r1, uint32_t& r2, uint32_t& r3,
                                      uint32_t addr) {
    asm volatile("ldmatrix.sync.aligned.m8n8.x4.shared.b16 {%0,%1,%2,%3}, [%4];"
                 : "=r"(r0), "=r"(r1), "=r"(r2), "=r"(r3) : "r"(addr));
}
__device__ __forceinline__ void mma16816(float* c, const uint32_t* a, const uint32_t* b) {
    asm volatile(
        "mma.sync.aligned.m16n8k16.row.col.f32.f16.f16.f32 "
        "{%0,%1,%2,%3}, {%4,%5,%6,%7}, {%8,%9}, {%0,%1,%2,%3};"
        : "+f"(c[0]), "+f"(c[1]), "+f"(c[2]), "+f"(c[3])
        : "r"(a[0]), "r"(a[1]), "r"(a[2]), "r"(a[3]), "r"(b[0]), "r"(b[1]));
}
__device__ __forceinline__ void hsplit(float v, __half& h, __half& l) {
    h = __float2half_rn(v);
    l = __float2half_rn(v - __half2float(h));
}

// ---------------- CSR build ----------------
__global__ void count_kernel(const int* __restrict__ dst, int e, int* __restrict__ cnt) {
    int i = blockIdx.x * blockDim.x + threadIdx.x;
    if (i < e) atomicAdd(&cnt[dst[i]], 1);
}

// --- multi-block scan: phase 1 (per-block sums; block = 256 thr x 16 elems) ---
__global__ void scan1_kernel(const int* __restrict__ cnt, int n, int* __restrict__ bsum) {
    int tid = threadIdx.x;
    int base = (blockIdx.x * 256 + tid) * 16;
    int s = 0;
#pragma unroll
    for (int i = 0; i < 16; i++) {
        int idx = base + i;
        if (idx < n) s += cnt[idx];
    }
    __shared__ int sh[8];
#pragma unroll
    for (int o = 16; o; o >>= 1) s += __shfl_down_sync(0xffffffffu, s, o);
    if ((tid & 31) == 0) sh[tid >> 5] = s;
    __syncthreads();
    if (tid < 8) {
        int v = sh[tid];
#pragma unroll
        for (int o = 4; o; o >>= 1) v += __shfl_down_sync(0xffu, v, o);
        if (tid == 0) bsum[blockIdx.x] = v;
    }
}

// --- phase 2: single-warp exclusive scan of block sums (nb <= 32) ---
__global__ void scan2_kernel(int* __restrict__ bsum, int nb, int* __restrict__ rowptr, int n) {
    int tid = threadIdx.x;
    int v = (tid < nb) ? bsum[tid] : 0;
    int orig = v;
#pragma unroll
    for (int o = 1; o < 32; o <<= 1) {
        int t = __shfl_up_sync(0xffffffffu, v, o);
        if (tid >= o) v += t;
    }
    if (tid < nb) bsum[tid] = v - orig;
    if (tid == 31) rowptr[n] = v;
}

// --- phase 3: per-element exclusive prefix + cursor + dis ---
__global__ void scan3_kernel(const int* __restrict__ cnt, int n, const int* __restrict__ bsum,
                             int* __restrict__ rowptr, int* __restrict__ cursor,
                             float* __restrict__ dis) {
    int tid = threadIdx.x;
    int lane = tid & 31, warp = tid >> 5;
    int base = (blockIdx.x * 256 + tid) * 16;
    int vals[16];
    int s = 0;
#pragma unroll
    for (int i = 0; i < 16; i++) {
        int idx = base + i;
        vals[i] = (idx < n) ? cnt[idx] : 0;
        s += vals[i];
    }
    int incl = s;
#pragma unroll
    for (int o = 1; o < 32; o <<= 1) {
        int t = __shfl_up_sync(0xffffffffu, incl, o);
        if (lane >= o) incl += t;
    }
    __shared__ int wsum[8];
    if (lane == 31) wsum[warp] = incl;
    __syncthreads();
    int woff = 0;
    for (int w = 0; w < warp; w++) woff += wsum[w];
    int excl = bsum[blockIdx.x] + woff + (incl - s);
#pragma unroll
    for (int i = 0; i < 16; i++) {
        int idx = base + i;
        if (idx < n) {
            rowptr[idx] = excl;
            cursor[idx] = excl;
            dis[idx] = rsqrtf((float)(vals[i] + 1));
            excl += vals[i];
        }
    }
}

__global__ void fill_kernel(const int* __restrict__ src, const int* __restrict__ dst, int e,
                            int* __restrict__ cursor, int* __restrict__ csrsrc,
                            float* __restrict__ csrnorm, const float* __restrict__ dis) {
    int i = blockIdx.x * blockDim.x + threadIdx.x;
    if (i >= e) return;
    int d = dst[i], s = src[i];
    int p = atomicAdd(&cursor[d], 1);
    csrsrc[p] = s;
    csrnorm[p] = dis[s] * dis[d];
}

// ---------------- weight conversion (transpose + single fp16) ----------------
__global__ void convw_kernel(const float* __restrict__ W1, const float* __restrict__ W3,
                             const float* __restrict__ W2, const float* __restrict__ W4,
                             const float* __restrict__ W7, const float* __restrict__ b1,
                             const float* __restrict__ b3,
                             __half* WcT, __half* W2T, __half* W4T, __half* W7T,
                             float* bc) {
    int i = blockIdx.x * blockDim.x + threadIdx.x;
    if (i < 256) bc[i] = (i < 128) ? b1[i] : b3[i - 128];
    float v;
    __half* o;
    int off;
    if (i < 16384) {                      // WcT [256][64]
        int c = i >> 6, k = i & 63;
        v = (c < 128) ? W1[k * 128 + c] : W3[k * 128 + (c - 128)];
        o = WcT; off = i;
    } else if (i < 49152) {               // W2T [256][128]
        int j = i - 16384; int c = j >> 7, k = j & 127;
        v = W2[k * 256 + c]; o = W2T; off = j;
    } else if (i < 81920) {               // W4T [256][128]
        int j = i - 49152; int c = j >> 7, k = j & 127;
        v = W4[k * 256 + c]; o = W4T; off = j;
    } else if (i < 122880) {              // W7T [128][320]
        int j = i - 81920; int c = j / 320, k = j % 320;
        v = (k < 256) ? W7[(size_t)(256 + k) * 128 + c]
                      : W7[(size_t)(512 + (k - 256)) * 128 + c];
        o = W7T; off = j;
    } else return;
    o[off] = __float2half_rn(v);
}

// x -> fp16 hi/lo into cols 256:320 of Vh/Vl (ld=320)
__global__ void convx_kernel(const float* __restrict__ x, __half* __restrict__ Vh,
                             __half* __restrict__ Vl, int total) {
    int i = blockIdx.x * blockDim.x + threadIdx.x;
    if (i >= total) return;
    int row = i >> 6, c = i & 63;
    __half h, l;
    hsplit(x[i], h, l);
    Vh[(size_t)row * 320 + 256 + c] = h;
    Vl[(size_t)row * 320 + 256 + c] = l;
}

// ---------------- shared HMMA mainloop (2-segment fp16 split, B single) ----------------
__device__ __forceinline__ void gemm_mainloop(
    const __half* __restrict__ Ahi, const __half* __restrict__ Alo, int lda,
    const __half* __restrict__ B,
    int K, int n, int rowBase, int colBase,
    __half (*As)[128 * 40], __half (*Bs)[128 * 40],
    float acc[4][4][4]) {
    int tid = threadIdx.x;
    int lane = tid & 31, warp = tid >> 5;
    int warpM = warp & 1, warpN = warp >> 1;

    int segsz = K >> 5;
    int total = 2 * segsz;

    auto loadChunk = [&](int tc, int buf) {
        int seg = tc / segsz, kc = tc % segsz;
        const __half* Ab = seg ? Alo : Ahi;
        int k0 = kc << 5;
        uint32_t aB = smem_u32(&As[buf][0]);
        uint32_t bB = smem_u32(&Bs[buf][0]);
#pragma unroll
        for (int i = 0; i < 2; i++) {
            int idx = tid + (i << 8);
            int row = idx >> 2, quad = idx & 3;
            cpasync16(aB + (row * 40 + quad * 8) * 2,
                      Ab + (size_t)(rowBase + row) * lda + k0 + quad * 8,
                      (rowBase + row) < n);
            cpasync16(bB + (row * 40 + quad * 8) * 2,
                      B + (size_t)(colBase + row) * K + k0 + quad * 8, true);
        }
        asm volatile("cp.async.commit_group;");
    };

    auto compute = [&](int buf) {
        uint32_t aB = smem_u32(&As[buf][0]);
        uint32_t bB = smem_u32(&Bs[buf][0]);
#pragma unroll
        for (int ks = 0; ks < 2; ks++) {
            uint32_t af[4][4], bf[4][2];
            int arow = warpM * 64 + (lane & 15);
            int acol = ks * 16 + (lane >> 4) * 8;
#pragma unroll
            for (int mi = 0; mi < 4; mi++)
                ldmx4(af[mi][0], af[mi][1], af[mi][2], af[mi][3],
                      aB + ((arow + mi * 16) * 40 + acol) * 2);
#pragma unroll
            for (int np = 0; np < 2; np++) {
                int brow = warpN * 32 + np * 16 + (lane & 7) + ((lane >> 4) << 3);
                int bcol = ks * 16 + (((lane >> 3) & 1) << 3);
                ldmx4(bf[np * 2][0], bf[np * 2][1], bf[np * 2 + 1][0], bf[np * 2 + 1][1],
                      bB + (brow * 40 + bcol) * 2);
            }
#pragma unroll
            for (int mi = 0; mi < 4; mi++)
#pragma unroll
                for (int ni = 0; ni < 4; ni++) mma16816(acc[mi][ni], af[mi], bf[ni]);
        }
    };

    loadChunk(0, 0);
    for (int tc = 0; tc < total; tc++) {
        int buf = tc & 1;
        if (tc + 1 < total) {
            loadChunk(tc + 1, buf ^ 1);
            asm volatile("cp.async.wait_group 1;");
        } else {
            asm volatile("cp.async.wait_group 0;");
        }
        __syncthreads();
        compute(buf);
        __syncthreads();
    }
}

// ---------------- epilogue device functions ----------------
__device__ __forceinline__ void epi_colmax(float acc[4][4][4], int n, int rBase, int cBase,
                                           int lane, const float* __restrict__ addvec,
                                           int* __restrict__ mv) {
    float cm[8];
#pragma unroll
    for (int j = 0; j < 8; j++) cm[j] = -1e30f;
#pragma unroll
    for (int mi = 0; mi < 4; mi++) {
        int r0 = rBase + mi * 16 + (lane >> 2);
        int r1 = r0 + 8;
#pragma unroll
        for (int ni = 0; ni < 4; ni++) {
            int col = cBase + ni * 8 + (lane & 3) * 2;
            float v0 = (r0 < n) ? tanhf(acc[mi][ni][0] + addvec[col]) : -1e30f;
            float v1 = (r0 < n) ? tanhf(acc[mi][ni][1] + addvec[col + 1]) : -1e30f;
            float v2 = (r1 < n) ? tanhf(acc[mi][ni][2] + addvec[col]) : -1e30f;
            float v3 = (r1 < n) ? tanhf(acc[mi][ni][3] + addvec[col + 1]) : -1e30f;
            cm[ni * 2] = fmaxf(cm[ni * 2], fmaxf(v0, v2));
            cm[ni * 2 + 1] = fmaxf(cm[ni * 2 + 1], fmaxf(v1, v3));
        }
    }
#pragma unroll
    for (int off = 4; off < 32; off <<= 1)
#pragma unroll
        for (int j = 0; j < 8; j++)
            cm[j] = fmaxf(cm[j], __shfl_xor_sync(0xffffffffu, cm[j], off));
    if (lane < 4) {
#pragma unroll
        for (int ni = 0; ni < 4; ni++) {
            int col = cBase + ni * 8 + lane * 2;
            atomicMax(&mv[col], __float_as_int(cm[ni * 2] + 2.0f));
            atomicMax(&mv[col + 1], __float_as_int(cm[ni * 2 + 1] + 2.0f));
        }
    }
}

// mode 0: tanh+bias -> C f32 | mode 2: tanh+bias -> fp16 hi/lo | mode 3: +addvec -> C f32
template <int MODE>
__device__ __forceinline__ void epi_store(float acc[4][4][4], int n, int rBase, int cBase,
                                          int lane, const float* __restrict__ addvec,
                                          float* __restrict__ C, int ldC,
                                          __half* __restrict__ outHi,
                                          __half* __restrict__ outLo, int ldO) {
#pragma unroll
    for (int mi = 0; mi < 4; mi++) {
#pragma unroll
        for (int h = 0; h < 2; h++) {
            int r = rBase + mi * 16 + (lane >> 2) + h * 8;
            if (r >= n) continue;
#pragma unroll
            for (int ni = 0; ni < 4; ni++) {
                int col = cBase + ni * 8 + (lane & 3) * 2;
                float v0 = acc[mi][ni][h * 2], v1 = acc[mi][ni][h * 2 + 1];
                if (MODE == 0) {
                    v0 = tanhf(v0 + addvec[col]);
                    v1 = tanhf(v1 + addvec[col + 1]);
                    *(float2*)(C + (size_t)r * ldC + col) = make_float2(v0, v1);
                } else if (MODE == 2) {
                    v0 = tanhf(v0 + addvec[col]);
                    v1 = tanhf(v1 + addvec[col + 1]);
                    __half h0, l0, h1, l1;
                    hsplit(v0, h0, l0);
                    hsplit(v1, h1, l1);
                    *(__half2*)(outHi + (size_t)r * ldO + col) = __halves2half2(h0, h1);
                    *(__half2*)(outLo + (size_t)r * ldO + col) = __halves2half2(l0, l1);
                } else {
                    v0 += addvec[col];
                    v1 += addvec[col + 1];
                    *(float2*)(C + (size_t)r * ldC + col) = make_float2(v0, v1);
                }
            }
        }
    }
}

// ---------------- standalone GEMMs (EPI 0 / 3) ----------------
template <int MODE>
__global__ __launch_bounds__(256)
void hmma_gemm(const __half* __restrict__ Ahi, const __half* __restrict__ Alo, int lda,
               const __half* __restrict__ B,
               int K, int n, float* __restrict__ C, int ldC,
               const float* __restrict__ addvec) {
    __shared__ __align__(16) __half As[2][128 * 40];
    __shared__ __align__(16) __half Bs[2][128 * 40];
    float acc[4][4][4];
#pragma unroll
    for (int a = 0; a < 4; a++)
#pragma unroll
        for (int b = 0; b < 4; b++)
#pragma unroll
            for (int c = 0; c < 4; c++) acc[a][b][c] = 0.0f;
    int rowBase = blockIdx.x * 128, colBase = blockIdx.y * 128;
    gemm_mainloop(Ahi, Alo, lda, B, K, n, rowBase, colBase, As, Bs, acc);
    int lane = threadIdx.x & 31, warp = threadIdx.x >> 5;
    int rBase = rowBase + (warp & 1) * 64, cBase = colBase + (warp >> 1) * 32;
    epi_store<MODE>(acc, n, rBase, cBase, lane, addvec, C, ldC, nullptr, nullptr, 0);
}

// ---------------- merged U/V GEMM (z=0: colmax; z=1: V -> fp16 split) ----------------
__global__ __launch_bounds__(256)
void hmma_gemm_uv(const __half* __restrict__ agg1h, const __half* __restrict__ agg1l,
                  const __half* __restrict__ W2T, const __half* __restrict__ W4T,
                  int n, const float* __restrict__ b2, const float* __restrict__ b4,
                  __half* __restrict__ Vh, __half* __restrict__ Vl,
                  int* __restrict__ mv) {
    __shared__ __align__(16) __half As[2][128 * 40];
    __shared__ __align__(16) __half Bs[2][128 * 40];
    float acc[4][4][4];
#pragma unroll
    for (int a = 0; a < 4; a++)
#pragma unroll
        for (int b = 0; b < 4; b++)
#pragma unroll
            for (int c = 0; c < 4; c++) acc[a][b][c] = 0.0f;
    int z = blockIdx.z;
    const __half* Ahi = agg1h + (z ? 128 : 0);
    const __half* Alo = agg1l + (z ? 128 : 0);
    const __half* B = z ? W4T : W2T;
    int rowBase = blockIdx.x * 128, colBase = blockIdx.y * 128;
    gemm_mainloop(Ahi, Alo, 256, B, 128, n, rowBase, colBase, As, Bs, acc);
    int lane = threadIdx.x & 31, warp = threadIdx.x >> 5;
    int rBase = rowBase + (warp & 1) * 64, cBase = colBase + (warp >> 1) * 32;
    if (z == 0) {
        epi_colmax(acc, n, rBase, cBase, lane, b2, mv);
    } else {
        epi_store<2>(acc, n, rBase, cBase, lane, b4, nullptr, 0, Vh, Vl, 320);
    }
}

// ---------------- agg F=64 (fp32 in -> fp16 hi/lo out) ----------------
__global__ void agg64_kernel(const float* __restrict__ h, const int* __restrict__ rowptr,
                             const int* __restrict__ csrsrc, const float* __restrict__ csrnorm,
                             const float* __restrict__ dis,
                             __half* __restrict__ outHi, __half* __restrict__ outLo, int n) {
    int warp = (blockIdx.x * blockDim.x + threadIdx.x) >> 5;
    int lane = threadIdx.x & 31;
    if (warp >= n) return;
    float2 acc = make_float2(0.f, 0.f);
    int s0 = rowptr[warp], s1 = rowptr[warp + 1];
    int j = s0;
    for (; j + 1 < s1; j += 2) {
        int sa = csrsrc[j], sb = csrsrc[j + 1];
        float wa = csrnorm[j], wb = csrnorm[j + 1];
        float2 va = *(const float2*)(h + (size_t)sa * 64 + lane * 2);
        float2 vb = *(const float2*)(h + (size_t)sb * 64 + lane * 2);
        acc.x += va.x * wa + vb.x * wb;
        acc.y += va.y * wa + vb.y * wb;
    }
    if (j < s1) {
        int s = csrsrc[j];
        float w = csrnorm[j];
        float2 va = *(const float2*)(h + (size_t)s * 64 + lane * 2);
        acc.x += va.x * w;
        acc.y += va.y * w;
    }
    float ds = dis[warp];
    float w2 = ds * ds;
    float2 v = *(const float2*)(h + (size_t)warp * 64 + lane * 2);
    acc.x += v.x * w2;
    acc.y += v.y * w2;
    __half h0, l0, h1, l1;
    hsplit(acc.x, h0, l0);
    hsplit(acc.y, h1, l1);
    *(__half2*)(outHi + (size_t)warp * 64 + lane * 2) = __halves2half2(h0, h1);
    *(__half2*)(outLo + (size_t)warp * 64 + lane * 2) = __halves2half2(l0, l1);
}

// ---------------- agg F=256 (fp32 in -> fp16 hi/lo out) ----------------
__global__ void agg256_kernel(const float* __restrict__ h, const int* __restrict__ rowptr,
                              const int* __restrict__ csrsrc, const float* __restrict__ csrnorm,
                              const float* __restrict__ dis,
                              __half* __restrict__ outHi, __half* __restrict__ outLo, int n) {
    int warp = (blockIdx.x * blockDim.x + threadIdx.x) >> 5;
    int lane = threadIdx.x & 31;
    if (warp >= n) return;
    float4 a0 = make_float4(0.f, 0.f, 0.f, 0.f), a1 = a0;
    int s0 = rowptr[warp], s1 = rowptr[warp + 1];
    int i0 = lane << 2, i1 = (lane + 32) << 2;
    for (int j = s0; j < s1; j++) {
        int s = csrsrc[j];
        float w = csrnorm[j];
        const float* hp = h + (size_t)s * 256;
        float4 v0 = *(const float4*)(hp + i0);
        float4 v1 = *(const float4*)(hp + i1);
        a0.x += v0.x * w; a0.y += v0.y * w; a0.z += v0.z * w; a0.w += v0.w * w;
        a1.x += v1.x * w; a1.y += v1.y * w; a1.z += v1.z * w; a1.w += v1.w * w;
    }
    float ds = dis[warp];
    float w2 = ds * ds;
    const float* hp = h + (size_t)warp * 256;
    float4 v0 = *(const float4*)(hp + i0);
    float4 v1 = *(const float4*)(hp + i1);
    a0.x += v0.x * w2; a0.y += v0.y * w2; a0.z += v0.z * w2; a0.w += v0.w * w2;
    a1.x += v1.x * w2; a1.y += v1.y * w2; a1.z += v1.z * w2; a1.w += v1.w * w2;
    __half h0, l0, h1, l1, h2, l2, h3, l3;
    hsplit(a0.x, h0, l0); hsplit(a0.y, h1, l1); hsplit(a0.z, h2, l2); hsplit(a0.w, h3, l3);
    *(__half2*)(outHi + (size_t)warp * 256 + i0) = __halves2half2(h0, h1);
    *(__half2*)(outHi + (size_t)warp * 256 + i0 + 2) = __halves2half2(h2, h3);
    *(__half2*)(outLo + (size_t)warp * 256 + i0) = __halves2half2(l0, l1);
    *(__half2*)(outLo + (size_t)warp * 256 + i0 + 2) = __halves2half2(l2, l3);
    hsplit(a1.x, h0, l0); hsplit(a1.y, h1, l1); hsplit(a1.z, h2, l2); hsplit(a1.w, h3, l3);
    *(__half2*)(outHi + (size_t)warp * 256 + i1) = __halves2half2(h0, h1);
    *(__half2*)(outHi + (size_t)warp * 256 + i1 + 2) = __halves2half2(h2, h3);
    *(__half2*)(outLo + (size_t)warp * 256 + i1) = __halves2half2(l0, l1);
    *(__half2*)(outLo + (size_t)warp * 256 + i1 + 2) = __halves2half2(l2, l3);
}

// ---------------- agg F=128 + bias + tanh (final, fp32) ----------------
__global__ void agg128t_kernel(const float* __restrict__ h, const int* __restrict__ rowptr,
                               const int* __restrict__ csrsrc, const float* __restrict__ csrnorm,
                               const float* __restrict__ dis, const float* __restrict__ bias,
                               float* __restrict__ out, int n) {
    int warp = (blockIdx.x * blockDim.x + threadIdx.x) >> 5;
    int lane = threadIdx.x & 31;
    if (warp >= n) return;
    float4 acc = make_float4(0.f, 0.f, 0.f, 0.f);
    int s0 = rowptr[warp], s1 = rowptr[warp + 1];
    int idx = lane << 2;
    int j = s0;
    for (; j + 1 < s1; j += 2) {
        int sa = csrsrc[j], sb = csrsrc[j + 1];
        float wa = csrnorm[j], wb = csrnorm[j + 1];
        float4 va = *(const float4*)(h + (size_t)sa * 128 + idx);
        float4 vb = *(const float4*)(h + (size_t)sb * 128 + idx);
        acc.x += va.x * wa + vb.x * wb;
        acc.y += va.y * wa + vb.y * wb;
        acc.z += va.z * wa + vb.z * wb;
        acc.w += va.w * wa + vb.w * wb;
    }
    if (j < s1) {
        int s = csrsrc[j];
        float w = csrnorm[j];
        float4 va = *(const float4*)(h + (size_t)s * 128 + idx);
        acc.x += va.x * w; acc.y += va.y * w; acc.z += va.z * w; acc.w += va.w * w;
    }
    float ds = dis[warp];
    float w2 = ds * ds;
    float4 v = *(const float4*)(h + (size_t)warp * 128 + idx);
    float4 bb = *(const float4*)(bias + idx);
    float4 r;
    r.x = tanhf(acc.x + v.x * w2 + bb.x);
    r.y = tanhf(acc.y + v.y * w2 + bb.y);
    r.z = tanhf(acc.z + v.z * w2 + bb.z);
    r.w = tanhf(acc.w + v.w * w2 + bb.w);
    *(float4*)(out + (size_t)warp * 128 + idx) = r;
}

// ---------------- cvec = (colmax of U) @ W7[0:256,:] ----------------
__global__ void cvec_kernel(const int* __restrict__ mv, const float* __restrict__ W7,
                            float* __restrict__ cvec) {
    int j = threadIdx.x;
    float s = 0.0f;
    for (int k = 0; k < 256; k++)
        s += (__int_as_float(mv[k]) - 2.0f) * W7[(size_t)k * 128 + j];
    cvec[j] = s;
}

extern "C" void kernel_launch(void* const* d_in, const int* in_sizes, int n_in,
                              void* d_out, int out_size) {
    const float* x = (const float*)d_in[0];
    const int* ei = (const int*)d_in[1];
    const float* W1 = (const float*)d_in[3];
    const float* b1 = (const float*)d_in[4];
    const float* W2 = (const float*)d_in[5];
    const float* b2 = (const float*)d_in[6];
    const float* W3 = (const float*)d_in[7];
    const float* b3 = (const float*)d_in[8];
    const float* W4 = (const float*)d_in[9];
    const float* b4 = (const float*)d_in[10];
    const float* W7 = (const float*)d_in[11];
    const float* b7 = (const float*)d_in[12];

    int n = in_sizes[0] / 64;
    int e = in_sizes[1] / 2;
    const int* src = ei;
    const int* dst = ei + e;
    float* out = (float*)d_out;

    __half *agg0h, *agg0l, *agg1h, *agg1l, *Vh, *Vl, *WcT, *W2T, *W4T, *W7T;
    float *T1, *H, *dis, *csrnorm, *cvec, *bc;
    int *cnt, *rowptr, *cursor, *csrsrc, *mv, *bsum;
    cudaGetSymbolAddress((void**)&agg0h, g_agg0h);
    cudaGetSymbolAddress((void**)&agg0l, g_agg0l);
    cudaGetSymbolAddress((void**)&T1, g_T1);
    cudaGetSymbolAddress((void**)&agg1h, g_agg1h);
    cudaGetSymbolAddress((void**)&agg1l, g_agg1l);
    cudaGetSymbolAddress((void**)&Vh, g_Vh);
    cudaGetSymbolAddress((void**)&Vl, g_Vl);
    cudaGetSymbolAddress((void**)&H, g_H);
    cudaGetSymbolAddress((void**)&dis, g_dis);
    cudaGetSymbolAddress((void**)&cnt, g_cnt);
    cudaGetSymbolAddress((void**)&rowptr, g_rowptr);
    cudaGetSymbolAddress((void**)&cursor, g_cursor);
    cudaGetSymbolAddress((void**)&csrsrc, g_csrsrc);
    cudaGetSymbolAddress((void**)&csrnorm, g_csrnorm);
    cudaGetSymbolAddress((void**)&bsum, g_bsum);
    cudaGetSymbolAddress((void**)&mv, g_mv);
    cudaGetSymbolAddress((void**)&cvec, g_cvec);
    cudaGetSymbolAddress((void**)&WcT, g_WcT);
    cudaGetSymbolAddress((void**)&W2T, g_W2T);
    cudaGetSymbolAddress((void**)&W4T, g_W4T);
    cudaGetSymbolAddress((void**)&W7T, g_W7T);
    cudaGetSymbolAddress((void**)&bc, g_bc);

    int eb = (e + 255) / 256;
    int aggBlocks = (n + 7) / 8;
    int gm = (n + 127) / 128;
    int nb = (n + 4095) / 4096;
    dim3 g2(gm, 2), g1(gm, 1), guv(gm, 2, 2);

    // CSR build + conversions
    cudaMemsetAsync(cnt, 0, (size_t)n * sizeof(int));
    cudaMemsetAsync(mv, 0, 256 * sizeof(int));
    convw_kernel<<<480, 256>>>(W1, W3, W2, W4, W7, b1, b3, WcT, W2T, W4T, W7T, bc);
    convx_kernel<<<(n * 64 + 255) / 256, 256>>>(x, Vh, Vl, n * 64);
    count_kernel<<<eb, 256>>>(dst, e, cnt);
    scan1_kernel<<<nb, 256>>>(cnt, n, bsum);
    scan2_kernel<<<1, 32>>>(bsum, nb, rowptr, n);
    scan3_kernel<<<nb, 256>>>(cnt, n, bsum, rowptr, cursor, dis);
    fill_kernel<<<eb, 256>>>(src, dst, e, cursor, csrsrc, csrnorm, dis);

    // agg0 = P x (shared conv1/conv3), split to fp16
    agg64_kernel<<<aggBlocks, 256>>>(x, rowptr, csrsrc, csrnorm, dis, agg0h, agg0l, n);
    // T1 = tanh(agg0 @ [W1|W3] + [b1|b3])
    hmma_gemm<0><<<g2, 256>>>(agg0h, agg0l, 64, WcT, 64, n, T1, 256, bc);
    // agg1 = P T1, split to fp16
    agg256_kernel<<<aggBlocks, 256>>>(T1, rowptr, csrsrc, csrnorm, dis, agg1h, agg1l, n);
    // merged: z=0 colmax(tanh(agg1[:,:128]@W2+b2)) -> mv; z=1 V=tanh(agg1[:,128:]@W4+b4)
    hmma_gemm_uv<<<guv, 256>>>(agg1h, agg1l, W2T, W4T, n, b2, b4, Vh, Vl, mv);
    // cvec = colmax @ W7[0:256]
    cvec_kernel<<<1, 128>>>(mv, W7, cvec);
    // H = [V | x] @ [W7b; W7c] + cvec   (single K=320 GEMM)
    hmma_gemm<3><<<g1, 256>>>(Vh, Vl, 320, W7T, 320, n, H, 128, cvec);
    // out = tanh(P H + b7)
    agg128t_kernel<<<aggBlocks, 256>>>(H, rowptr, csrsrc, csrnorm, dis, b7, out, n);
}

// round 7
// speedup vs baseline: 5.2366x; 1.3286x over previous
#include <cuda_runtime.h>
#include <cuda_fp16.h>
#include <math.h>
#include <stdint.h>

#define MAXN 50000
#define MAXE 400000

// ---------------- static scratch (all intermediates fp16) ----------------
__device__ __half g_xh[MAXN * 64];       // x in fp16 (gather source)
__device__ __half g_agg0[MAXN * 64];     // P x
__device__ __half g_T1[MAXN * 256];      // tanh((Px)[W1|W3]+b)
__device__ __half g_agg1[MAXN * 256];    // P T1
__device__ __half g_Vf[MAXN * 320];      // V (0:256) | xh (256:320)
__device__ __half g_H[MAXN * 128];       // pre-final linear
__device__ float g_dis[MAXN];
__device__ int g_cnt[MAXN], g_rowptr[MAXN + 1], g_cursor[MAXN], g_csrsrc[MAXE];
__device__ float g_csrnorm[MAXE];
__device__ int g_bsum[64];
__device__ int g_mv[256];
__device__ float g_cvec[128];
__device__ __half g_WcT[256 * 64];
__device__ __half g_W2T[256 * 128];
__device__ __half g_W4T[256 * 128];
__device__ __half g_W7T[128 * 320];
__device__ float g_bc[256];

// ---------------- helpers ----------------
__device__ __forceinline__ uint32_t smem_u32(const void* p) {
    uint32_t a;
    asm("{ .reg .u64 t; cvta.to.shared.u64 t, %1; cvt.u32.u64 %0, t; }" : "=r"(a) : "l"(p));
    return a;
}
__device__ __forceinline__ void cpasync16(uint32_t dst, const void* src, bool pred) {
    int sz = pred ? 16 : 0;  // src-size 0 => zero-fill
    asm volatile("cp.async.cg.shared.global [%0], [%1], 16, %2;\n" :: "r"(dst), "l"(src), "r"(sz));
}
__device__ __forceinline__ void ldmx4(uint32_t& r0, uint32_t& r1, uint32_t& r2, uint32_t& r3,
                                      uint32_t addr) {
    asm volatile("ldmatrix.sync.aligned.m8n8.x4.shared.b16 {%0,%1,%2,%3}, [%4];"
                 : "=r"(r0), "=r"(r1), "=r"(r2), "=r"(r3) : "r"(addr));
}
__device__ __forceinline__ void mma16816(float* c, const uint32_t* a, const uint32_t* b) {
    asm volatile(
        "mma.sync.aligned.m16n8k16.row.col.f32.f16.f16.f32 "
        "{%0,%1,%2,%3}, {%4,%5,%6,%7}, {%8,%9}, {%0,%1,%2,%3};"
        : "+f"(c[0]), "+f"(c[1]), "+f"(c[2]), "+f"(c[3])
        : "r"(a[0]), "r"(a[1]), "r"(a[2]), "r"(a[3]), "r"(b[0]), "r"(b[1]));
}

// ---------------- CSR build ----------------
__global__ void count_kernel(const int* __restrict__ dst, int e, int* __restrict__ cnt) {
    int i = blockIdx.x * blockDim.x + threadIdx.x;
    if (i < e) atomicAdd(&cnt[dst[i]], 1);
}

__global__ void scan1_kernel(const int* __restrict__ cnt, int n, int* __restrict__ bsum) {
    int tid = threadIdx.x;
    int base = (blockIdx.x * 256 + tid) * 16;
    int s = 0;
#pragma unroll
    for (int i = 0; i < 16; i++) {
        int idx = base + i;
        if (idx < n) s += cnt[idx];
    }
    __shared__ int sh[8];
#pragma unroll
    for (int o = 16; o; o >>= 1) s += __shfl_down_sync(0xffffffffu, s, o);
    if ((tid & 31) == 0) sh[tid >> 5] = s;
    __syncthreads();
    if (tid < 8) {
        int v = sh[tid];
#pragma unroll
        for (int o = 4; o; o >>= 1) v += __shfl_down_sync(0xffu, v, o);
        if (tid == 0) bsum[blockIdx.x] = v;
    }
}

__global__ void scan2_kernel(int* __restrict__ bsum, int nb, int* __restrict__ rowptr, int n) {
    int tid = threadIdx.x;
    int v = (tid < nb) ? bsum[tid] : 0;
    int orig = v;
#pragma unroll
    for (int o = 1; o < 32; o <<= 1) {
        int t = __shfl_up_sync(0xffffffffu, v, o);
        if (tid >= o) v += t;
    }
    if (tid < nb) bsum[tid] = v - orig;
    if (tid == 31) rowptr[n] = v;
}

__global__ void scan3_kernel(const int* __restrict__ cnt, int n, const int* __restrict__ bsum,
                             int* __restrict__ rowptr, int* __restrict__ cursor,
                             float* __restrict__ dis) {
    int tid = threadIdx.x;
    int lane = tid & 31, warp = tid >> 5;
    int base = (blockIdx.x * 256 + tid) * 16;
    int vals[16];
    int s = 0;
#pragma unroll
    for (int i = 0; i < 16; i++) {
        int idx = base + i;
        vals[i] = (idx < n) ? cnt[idx] : 0;
        s += vals[i];
    }
    int incl = s;
#pragma unroll
    for (int o = 1; o < 32; o <<= 1) {
        int t = __shfl_up_sync(0xffffffffu, incl, o);
        if (lane >= o) incl += t;
    }
    __shared__ int wsum[8];
    if (lane == 31) wsum[warp] = incl;
    __syncthreads();
    int woff = 0;
    for (int w = 0; w < warp; w++) woff += wsum[w];
    int excl = bsum[blockIdx.x] + woff + (incl - s);
#pragma unroll
    for (int i = 0; i < 16; i++) {
        int idx = base + i;
        if (idx < n) {
            rowptr[idx] = excl;
            cursor[idx] = excl;
            dis[idx] = rsqrtf((float)(vals[i] + 1));
            excl += vals[i];
        }
    }
}

__global__ void fill_kernel(const int* __restrict__ src, const int* __restrict__ dst, int e,
                            int* __restrict__ cursor, int* __restrict__ csrsrc,
                            float* __restrict__ csrnorm, const float* __restrict__ dis) {
    int i = blockIdx.x * blockDim.x + threadIdx.x;
    if (i >= e) return;
    int d = dst[i], s = src[i];
    int p = atomicAdd(&cursor[d], 1);
    csrsrc[p] = s;
    csrnorm[p] = dis[s] * dis[d];
}

// ---------------- weight conversion ----------------
__global__ void convw_kernel(const float* __restrict__ W1, const float* __restrict__ W3,
                             const float* __restrict__ W2, const float* __restrict__ W4,
                             const float* __restrict__ W7, const float* __restrict__ b1,
                             const float* __restrict__ b3,
                             __half* WcT, __half* W2T, __half* W4T, __half* W7T,
                             float* bc) {
    int i = blockIdx.x * blockDim.x + threadIdx.x;
    if (i < 256) bc[i] = (i < 128) ? b1[i] : b3[i - 128];
    float v;
    __half* o;
    int off;
    if (i < 16384) {                      // WcT [256][64]
        int c = i >> 6, k = i & 63;
        v = (c < 128) ? W1[k * 128 + c] : W3[k * 128 + (c - 128)];
        o = WcT; off = i;
    } else if (i < 49152) {               // W2T [256][128]
        int j = i - 16384; int c = j >> 7, k = j & 127;
        v = W2[k * 256 + c]; o = W2T; off = j;
    } else if (i < 81920) {               // W4T [256][128]
        int j = i - 49152; int c = j >> 7, k = j & 127;
        v = W4[k * 256 + c]; o = W4T; off = j;
    } else if (i < 122880) {              // W7T [128][320]
        int j = i - 81920; int c = j / 320, k = j % 320;
        v = (k < 256) ? W7[(size_t)(256 + k) * 128 + c]
                      : W7[(size_t)(512 + (k - 256)) * 128 + c];
        o = W7T; off = j;
    } else return;
    o[off] = __float2half_rn(v);
}

// x -> fp16: compact xh AND cols 256:320 of Vf (ld=320)
__global__ void convx_kernel(const float* __restrict__ x, __half* __restrict__ xh,
                             __half* __restrict__ Vf, int total) {
    int i = blockIdx.x * blockDim.x + threadIdx.x;
    if (i >= total) return;
    int row = i >> 6, c = i & 63;
    __half h = __float2half_rn(x[i]);
    xh[i] = h;
    Vf[(size_t)row * 320 + 256 + c] = h;
}

// ---------------- HMMA mainloop (pure fp16, single pass) ----------------
__device__ __forceinline__ void gemm_mainloop(
    const __half* __restrict__ A, int lda,
    const __half* __restrict__ B,
    int K, int n, int rowBase, int colBase,
    __half (*As)[128 * 40], __half (*Bs)[128 * 40],
    float acc[4][4][4]) {
    int tid = threadIdx.x;
    int lane = tid & 31, warp = tid >> 5;
    int warpM = warp & 1, warpN = warp >> 1;
    int total = K >> 5;

    auto loadChunk = [&](int kc, int buf) {
        int k0 = kc << 5;
        uint32_t aB = smem_u32(&As[buf][0]);
        uint32_t bB = smem_u32(&Bs[buf][0]);
#pragma unroll
        for (int i = 0; i < 2; i++) {
            int idx = tid + (i << 8);
            int row = idx >> 2, quad = idx & 3;
            cpasync16(aB + (row * 40 + quad * 8) * 2,
                      A + (size_t)(rowBase + row) * lda + k0 + quad * 8,
                      (rowBase + row) < n);
            cpasync16(bB + (row * 40 + quad * 8) * 2,
                      B + (size_t)(colBase + row) * K + k0 + quad * 8, true);
        }
        asm volatile("cp.async.commit_group;");
    };

    auto compute = [&](int buf) {
        uint32_t aB = smem_u32(&As[buf][0]);
        uint32_t bB = smem_u32(&Bs[buf][0]);
#pragma unroll
        for (int ks = 0; ks < 2; ks++) {
            uint32_t af[4][4], bf[4][2];
            int arow = warpM * 64 + (lane & 15);
            int acol = ks * 16 + (lane >> 4) * 8;
#pragma unroll
            for (int mi = 0; mi < 4; mi++)
                ldmx4(af[mi][0], af[mi][1], af[mi][2], af[mi][3],
                      aB + ((arow + mi * 16) * 40 + acol) * 2);
#pragma unroll
            for (int np = 0; np < 2; np++) {
                int brow = warpN * 32 + np * 16 + (lane & 7) + ((lane >> 4) << 3);
                int bcol = ks * 16 + (((lane >> 3) & 1) << 3);
                ldmx4(bf[np * 2][0], bf[np * 2][1], bf[np * 2 + 1][0], bf[np * 2 + 1][1],
                      bB + (brow * 40 + bcol) * 2);
            }
#pragma unroll
            for (int mi = 0; mi < 4; mi++)
#pragma unroll
                for (int ni = 0; ni < 4; ni++) mma16816(acc[mi][ni], af[mi], bf[ni]);
        }
    };

    loadChunk(0, 0);
    for (int tc = 0; tc < total; tc++) {
        int buf = tc & 1;
        if (tc + 1 < total) {
            loadChunk(tc + 1, buf ^ 1);
            asm volatile("cp.async.wait_group 1;");
        } else {
            asm volatile("cp.async.wait_group 0;");
        }
        __syncthreads();
        compute(buf);
        __syncthreads();
    }
}

// ---------------- epilogues ----------------
__device__ __forceinline__ void epi_colmax(float acc[4][4][4], int n, int rBase, int cBase,
                                           int lane, const float* __restrict__ addvec,
                                           int* __restrict__ mv) {
    float cm[8];
#pragma unroll
    for (int j = 0; j < 8; j++) cm[j] = -1e30f;
#pragma unroll
    for (int mi = 0; mi < 4; mi++) {
        int r0 = rBase + mi * 16 + (lane >> 2);
        int r1 = r0 + 8;
#pragma unroll
        for (int ni = 0; ni < 4; ni++) {
            int col = cBase + ni * 8 + (lane & 3) * 2;
            float v0 = (r0 < n) ? tanhf(acc[mi][ni][0] + addvec[col]) : -1e30f;
            float v1 = (r0 < n) ? tanhf(acc[mi][ni][1] + addvec[col + 1]) : -1e30f;
            float v2 = (r1 < n) ? tanhf(acc[mi][ni][2] + addvec[col]) : -1e30f;
            float v3 = (r1 < n) ? tanhf(acc[mi][ni][3] + addvec[col + 1]) : -1e30f;
            cm[ni * 2] = fmaxf(cm[ni * 2], fmaxf(v0, v2));
            cm[ni * 2 + 1] = fmaxf(cm[ni * 2 + 1], fmaxf(v1, v3));
        }
    }
#pragma unroll
    for (int off = 4; off < 32; off <<= 1)
#pragma unroll
        for (int j = 0; j < 8; j++)
            cm[j] = fmaxf(cm[j], __shfl_xor_sync(0xffffffffu, cm[j], off));
    if (lane < 4) {
#pragma unroll
        for (int ni = 0; ni < 4; ni++) {
            int col = cBase + ni * 8 + lane * 2;
            atomicMax(&mv[col], __float_as_int(cm[ni * 2] + 2.0f));
            atomicMax(&mv[col + 1], __float_as_int(cm[ni * 2 + 1] + 2.0f));
        }
    }
}

// MODE 0: tanh(acc+bias) -> half  |  MODE 1: acc+addvec -> half
template <int MODE>
__device__ __forceinline__ void epi_store_h(float acc[4][4][4], int n, int rBase, int cBase,
                                            int lane, const float* __restrict__ addvec,
                                            __half* __restrict__ outH, int ldO) {
#pragma unroll
    for (int mi = 0; mi < 4; mi++) {
#pragma unroll
        for (int h = 0; h < 2; h++) {
            int r = rBase + mi * 16 + (lane >> 2) + h * 8;
            if (r >= n) continue;
#pragma unroll
            for (int ni = 0; ni < 4; ni++) {
                int col = cBase + ni * 8 + (lane & 3) * 2;
                float v0 = acc[mi][ni][h * 2] + addvec[col];
                float v1 = acc[mi][ni][h * 2 + 1] + addvec[col + 1];
                if (MODE == 0) { v0 = tanhf(v0); v1 = tanhf(v1); }
                *(__half2*)(outH + (size_t)r * ldO + col) =
                    __halves2half2(__float2half_rn(v0), __float2half_rn(v1));
            }
        }
    }
}

// ---------------- standalone GEMM -> half out ----------------
template <int MODE>
__global__ __launch_bounds__(256)
void hmma_gemm(const __half* __restrict__ A, int lda, const __half* __restrict__ B,
               int K, int n, __half* __restrict__ outH, int ldO,
               const float* __restrict__ addvec) {
    __shared__ __align__(16) __half As[2][128 * 40];
    __shared__ __align__(16) __half Bs[2][128 * 40];
    float acc[4][4][4];
#pragma unroll
    for (int a = 0; a < 4; a++)
#pragma unroll
        for (int b = 0; b < 4; b++)
#pragma unroll
            for (int c = 0; c < 4; c++) acc[a][b][c] = 0.0f;
    int rowBase = blockIdx.x * 128, colBase = blockIdx.y * 128;
    gemm_mainloop(A, lda, B, K, n, rowBase, colBase, As, Bs, acc);
    int lane = threadIdx.x & 31, warp = threadIdx.x >> 5;
    int rBase = rowBase + (warp & 1) * 64, cBase = colBase + (warp >> 1) * 32;
    epi_store_h<MODE>(acc, n, rBase, cBase, lane, addvec, outH, ldO);
}

// ---------------- merged U/V GEMM (z=0: colmax; z=1: V -> half) ----------------
__global__ __launch_bounds__(256)
void hmma_gemm_uv(const __half* __restrict__ agg1,
                  const __half* __restrict__ W2T, const __half* __restrict__ W4T,
                  int n, const float* __restrict__ b2, const float* __restrict__ b4,
                  __half* __restrict__ Vf, int* __restrict__ mv) {
    __shared__ __align__(16) __half As[2][128 * 40];
    __shared__ __align__(16) __half Bs[2][128 * 40];
    float acc[4][4][4];
#pragma unroll
    for (int a = 0; a < 4; a++)
#pragma unroll
        for (int b = 0; b < 4; b++)
#pragma unroll
            for (int c = 0; c < 4; c++) acc[a][b][c] = 0.0f;
    int z = blockIdx.z;
    const __half* A = agg1 + (z ? 128 : 0);
    const __half* B = z ? W4T : W2T;
    int rowBase = blockIdx.x * 128, colBase = blockIdx.y * 128;
    gemm_mainloop(A, 256, B, 128, n, rowBase, colBase, As, Bs, acc);
    int lane = threadIdx.x & 31, warp = threadIdx.x >> 5;
    int rBase = rowBase + (warp & 1) * 64, cBase = colBase + (warp >> 1) * 32;
    if (z == 0) {
        epi_colmax(acc, n, rBase, cBase, lane, b2, mv);
    } else {
        epi_store_h<0>(acc, n, rBase, cBase, lane, b4, Vf, 320);
    }
}

// ---------------- agg F=64 (fp16 in -> fp16 out) ----------------
__global__ void agg64_kernel(const __half* __restrict__ h, const int* __restrict__ rowptr,
                             const int* __restrict__ csrsrc, const float* __restrict__ csrnorm,
                             const float* __restrict__ dis, __half* __restrict__ out, int n) {
    int warp = (blockIdx.x * blockDim.x + threadIdx.x) >> 5;
    int lane = threadIdx.x & 31;
    if (warp >= n) return;
    float2 acc = make_float2(0.f, 0.f);
    int s0 = rowptr[warp], s1 = rowptr[warp + 1];
    int j = s0;
    for (; j + 1 < s1; j += 2) {
        int sa = csrsrc[j], sb = csrsrc[j + 1];
        float wa = csrnorm[j], wb = csrnorm[j + 1];
        float2 va = __half22float2(*(const __half2*)(h + (size_t)sa * 64 + lane * 2));
        float2 vb = __half22float2(*(const __half2*)(h + (size_t)sb * 64 + lane * 2));
        acc.x += va.x * wa + vb.x * wb;
        acc.y += va.y * wa + vb.y * wb;
    }
    if (j < s1) {
        int s = csrsrc[j];
        float w = csrnorm[j];
        float2 va = __half22float2(*(const __half2*)(h + (size_t)s * 64 + lane * 2));
        acc.x += va.x * w;
        acc.y += va.y * w;
    }
    float ds = dis[warp];
    float w2 = ds * ds;
    float2 v = __half22float2(*(const __half2*)(h + (size_t)warp * 64 + lane * 2));
    acc.x += v.x * w2;
    acc.y += v.y * w2;
    *(__half2*)(out + (size_t)warp * 64 + lane * 2) =
        __halves2half2(__float2half_rn(acc.x), __float2half_rn(acc.y));
}

// ---------------- agg F=256 (fp16 in -> fp16 out) ----------------
__global__ void agg256_kernel(const __half* __restrict__ h, const int* __restrict__ rowptr,
                              const int* __restrict__ csrsrc, const float* __restrict__ csrnorm,
                              const float* __restrict__ dis, __half* __restrict__ out, int n) {
    int warp = (blockIdx.x * blockDim.x + threadIdx.x) >> 5;
    int lane = threadIdx.x & 31;
    if (warp >= n) return;
    float acc[8] = {0.f, 0.f, 0.f, 0.f, 0.f, 0.f, 0.f, 0.f};
    int s0 = rowptr[warp], s1 = rowptr[warp + 1];
    int i0 = lane * 8;
    for (int j = s0; j < s1; j++) {
        int s = csrsrc[j];
        float w = csrnorm[j];
        uint4 raw = *(const uint4*)(h + (size_t)s * 256 + i0);
        const __half2* hp = (const __half2*)&raw;
#pragma unroll
        for (int q = 0; q < 4; q++) {
            float2 f = __half22float2(hp[q]);
            acc[q * 2] += f.x * w;
            acc[q * 2 + 1] += f.y * w;
        }
    }
    float ds = dis[warp];
    float w2 = ds * ds;
    uint4 raw = *(const uint4*)(h + (size_t)warp * 256 + i0);
    const __half2* hp = (const __half2*)&raw;
#pragma unroll
    for (int q = 0; q < 4; q++) {
        float2 f = __half22float2(hp[q]);
        acc[q * 2] += f.x * w2;
        acc[q * 2 + 1] += f.y * w2;
    }
    uint4 o;
    __half2* op = (__half2*)&o;
#pragma unroll
    for (int q = 0; q < 4; q++)
        op[q] = __halves2half2(__float2half_rn(acc[q * 2]), __float2half_rn(acc[q * 2 + 1]));
    *(uint4*)(out + (size_t)warp * 256 + i0) = o;
}

// ---------------- agg F=128 + bias + tanh (fp16 in -> fp32 out) ----------------
__global__ void agg128t_kernel(const __half* __restrict__ h, const int* __restrict__ rowptr,
                               const int* __restrict__ csrsrc, const float* __restrict__ csrnorm,
                               const float* __restrict__ dis, const float* __restrict__ bias,
                               float* __restrict__ out, int n) {
    int warp = (blockIdx.x * blockDim.x + threadIdx.x) >> 5;
    int lane = threadIdx.x & 31;
    if (warp >= n) return;
    float4 acc = make_float4(0.f, 0.f, 0.f, 0.f);
    int s0 = rowptr[warp], s1 = rowptr[warp + 1];
    int idx = lane << 2;
    int j = s0;
    for (; j + 1 < s1; j += 2) {
        int sa = csrsrc[j], sb = csrsrc[j + 1];
        float wa = csrnorm[j], wb = csrnorm[j + 1];
        uint2 ra = *(const uint2*)(h + (size_t)sa * 128 + idx);
        uint2 rb = *(const uint2*)(h + (size_t)sb * 128 + idx);
        float2 a0 = __half22float2(*(const __half2*)&ra.x);
        float2 a1 = __half22float2(*(const __half2*)&ra.y);
        float2 b0 = __half22float2(*(const __half2*)&rb.x);
        float2 b1 = __half22float2(*(const __half2*)&rb.y);
        acc.x += a0.x * wa + b0.x * wb;
        acc.y += a0.y * wa + b0.y * wb;
        acc.z += a1.x * wa + b1.x * wb;
        acc.w += a1.y * wa + b1.y * wb;
    }
    if (j < s1) {
        int s = csrsrc[j];
        float w = csrnorm[j];
        uint2 ra = *(const uint2*)(h + (size_t)s * 128 + idx);
        float2 a0 = __half22float2(*(const __half2*)&ra.x);
        float2 a1 = __half22float2(*(const __half2*)&ra.y);
        acc.x += a0.x * w; acc.y += a0.y * w; acc.z += a1.x * w; acc.w += a1.y * w;
    }
    float ds = dis[warp];
    float w2 = ds * ds;
    uint2 rv = *(const uint2*)(h + (size_t)warp * 128 + idx);
    float2 v0 = __half22float2(*(const __half2*)&rv.x);
    float2 v1 = __half22float2(*(const __half2*)&rv.y);
    float4 bb = *(const float4*)(bias + idx);
    float4 r;
    r.x = tanhf(acc.x + v0.x * w2 + bb.x);
    r.y = tanhf(acc.y + v0.y * w2 + bb.y);
    r.z = tanhf(acc.z + v1.x * w2 + bb.z);
    r.w = tanhf(acc.w + v1.y * w2 + bb.w);
    *(float4*)(out + (size_t)warp * 128 + idx) = r;
}

// ---------------- cvec = (colmax of U) @ W7[0:256,:] ----------------
__global__ void cvec_kernel(const int* __restrict__ mv, const float* __restrict__ W7,
                            float* __restrict__ cvec) {
    int j = threadIdx.x;
    float s = 0.0f;
    for (int k = 0; k < 256; k++)
        s += (__int_as_float(mv[k]) - 2.0f) * W7[(size_t)k * 128 + j];
    cvec[j] = s;
}

extern "C" void kernel_launch(void* const* d_in, const int* in_sizes, int n_in,
                              void* d_out, int out_size) {
    const float* x = (const float*)d_in[0];
    const int* ei = (const int*)d_in[1];
    const float* W1 = (const float*)d_in[3];
    const float* b1 = (const float*)d_in[4];
    const float* W2 = (const float*)d_in[5];
    const float* b2 = (const float*)d_in[6];
    const float* W3 = (const float*)d_in[7];
    const float* b3 = (const float*)d_in[8];
    const float* W4 = (const float*)d_in[9];
    const float* b4 = (const float*)d_in[10];
    const float* W7 = (const float*)d_in[11];
    const float* b7 = (const float*)d_in[12];

    int n = in_sizes[0] / 64;
    int e = in_sizes[1] / 2;
    const int* src = ei;
    const int* dst = ei + e;
    float* out = (float*)d_out;

    __half *xh, *agg0, *T1, *agg1, *Vf, *H, *WcT, *W2T, *W4T, *W7T;
    float *dis, *csrnorm, *cvec, *bc;
    int *cnt, *rowptr, *cursor, *csrsrc, *mv, *bsum;
    cudaGetSymbolAddress((void**)&xh, g_xh);
    cudaGetSymbolAddress((void**)&agg0, g_agg0);
    cudaGetSymbolAddress((void**)&T1, g_T1);
    cudaGetSymbolAddress((void**)&agg1, g_agg1);
    cudaGetSymbolAddress((void**)&Vf, g_Vf);
    cudaGetSymbolAddress((void**)&H, g_H);
    cudaGetSymbolAddress((void**)&dis, g_dis);
    cudaGetSymbolAddress((void**)&cnt, g_cnt);
    cudaGetSymbolAddress((void**)&rowptr, g_rowptr);
    cudaGetSymbolAddress((void**)&cursor, g_cursor);
    cudaGetSymbolAddress((void**)&csrsrc, g_csrsrc);
    cudaGetSymbolAddress((void**)&csrnorm, g_csrnorm);
    cudaGetSymbolAddress((void**)&bsum, g_bsum);
    cudaGetSymbolAddress((void**)&mv, g_mv);
    cudaGetSymbolAddress((void**)&cvec, g_cvec);
    cudaGetSymbolAddress((void**)&WcT, g_WcT);
    cudaGetSymbolAddress((void**)&W2T, g_W2T);
    cudaGetSymbolAddress((void**)&W4T, g_W4T);
    cudaGetSymbolAddress((void**)&W7T, g_W7T);
    cudaGetSymbolAddress((void**)&bc, g_bc);

    int eb = (e + 255) / 256;
    int aggBlocks = (n + 7) / 8;
    int gm = (n + 127) / 128;
    int nb = (n + 4095) / 4096;
    dim3 g2(gm, 2), g1(gm, 1), guv(gm, 2, 2);

    // CSR build + conversions
    cudaMemsetAsync(cnt, 0, (size_t)n * sizeof(int));
    cudaMemsetAsync(mv, 0, 256 * sizeof(int));
    convw_kernel<<<480, 256>>>(W1, W3, W2, W4, W7, b1, b3, WcT, W2T, W4T, W7T, bc);
    convx_kernel<<<(n * 64 + 255) / 256, 256>>>(x, xh, Vf, n * 64);
    count_kernel<<<eb, 256>>>(dst, e, cnt);
    scan1_kernel<<<nb, 256>>>(cnt, n, bsum);
    scan2_kernel<<<1, 32>>>(bsum, nb, rowptr, n);
    scan3_kernel<<<nb, 256>>>(cnt, n, bsum, rowptr, cursor, dis);
    fill_kernel<<<eb, 256>>>(src, dst, e, cursor, csrsrc, csrnorm, dis);

    // agg0 = P x (shared conv1/conv3)
    agg64_kernel<<<aggBlocks, 256>>>(xh, rowptr, csrsrc, csrnorm, dis, agg0, n);
    // T1 = tanh(agg0 @ [W1|W3] + [b1|b3])
    hmma_gemm<0><<<g2, 256>>>(agg0, 64, WcT, 64, n, T1, 256, bc);
    // agg1 = P T1
    agg256_kernel<<<aggBlocks, 256>>>(T1, rowptr, csrsrc, csrnorm, dis, agg1, n);
    // merged: z=0 colmax(tanh(agg1[:,:128]@W2+b2)) -> mv; z=1 V=tanh(agg1[:,128:]@W4+b4)
    hmma_gemm_uv<<<guv, 256>>>(agg1, W2T, W4T, n, b2, b4, Vf, mv);
    // cvec = colmax @ W7[0:256]
    cvec_kernel<<<1, 128>>>(mv, W7, cvec);
    // H = [V | xh] @ [W7b; W7c] + cvec   (single K=320 GEMM)
    hmma_gemm<1><<<g1, 256>>>(Vf, 320, W7T, 320, n, H, 128, cvec);
    // out = tanh(P H + b7)
    agg128t_kernel<<<aggBlocks, 256>>>(H, rowptr, csrsrc, csrnorm, dis, b7, out, n);
}

// round 8
// speedup vs baseline: 5.4403x; 1.0389x over previous
#include <cuda_runtime.h>
#include <cuda_fp16.h>
#include <math.h>
#include <stdint.h>

#define MAXN 50000
#define MAXE 400000

// ---------------- static scratch (all intermediates fp16) ----------------
__device__ __half g_xh[MAXN * 64];
__device__ __half g_agg0[MAXN * 64];
__device__ __half g_T1[MAXN * 256];
__device__ __half g_agg1[MAXN * 256];
__device__ __half g_Vf[MAXN * 320];      // V (0:256) | xh (256:320)
__device__ __half g_H[MAXN * 128];
__device__ float g_dis[MAXN];
__device__ int g_cnt[MAXN], g_rowptr[MAXN + 1], g_cursor[MAXN], g_csrsrc[MAXE];
__device__ float g_csrnorm[MAXE];
__device__ int g_bsum[64];               // lookback slots (sum+1), zeroed per call
__device__ int g_mv[256];
__device__ __half g_WcT[256 * 64];
__device__ __half g_W2T[256 * 128];
__device__ __half g_W4T[256 * 128];
__device__ __half g_W7T[128 * 320];
__device__ float g_bc[256];

// ---------------- helpers ----------------
__device__ __forceinline__ uint32_t smem_u32(const void* p) {
    uint32_t a;
    asm("{ .reg .u64 t; cvta.to.shared.u64 t, %1; cvt.u32.u64 %0, t; }" : "=r"(a) : "l"(p));
    return a;
}
__device__ __forceinline__ void cpasync16(uint32_t dst, const void* src, bool pred) {
    int sz = pred ? 16 : 0;
    asm volatile("cp.async.cg.shared.global [%0], [%1], 16, %2;\n" :: "r"(dst), "l"(src), "r"(sz));
}
__device__ __forceinline__ void ldmx4(uint32_t& r0, uint32_t& r1, uint32_t& r2, uint32_t& r3,
                                      uint32_t addr) {
    asm volatile("ldmatrix.sync.aligned.m8n8.x4.shared.b16 {%0,%1,%2,%3}, [%4];"
                 : "=r"(r0), "=r"(r1), "=r"(r2), "=r"(r3) : "r"(addr));
}
__device__ __forceinline__ void mma16816(float* c, const uint32_t* a, const uint32_t* b) {
    asm volatile(
        "mma.sync.aligned.m16n8k16.row.col.f32.f16.f16.f32 "
        "{%0,%1,%2,%3}, {%4,%5,%6,%7}, {%8,%9}, {%0,%1,%2,%3};"
        : "+f"(c[0]), "+f"(c[1]), "+f"(c[2]), "+f"(c[3])
        : "r"(a[0]), "r"(a[1]), "r"(a[2]), "r"(a[3]), "r"(b[0]), "r"(b[1]));
}

// ---------------- CSR build ----------------
__global__ void count_kernel(const int* __restrict__ dst, int e, int* __restrict__ cnt) {
    int i = blockIdx.x * blockDim.x + threadIdx.x;
    if (i < e) atomicAdd(&cnt[dst[i]], 1);
}

// fused scan: per-block sums + lookback + per-element prefix (grid <= resident blocks!)
__global__ void scan_fused_kernel(const int* __restrict__ cnt, int n, int* __restrict__ bsum,
                                  int* __restrict__ rowptr, int* __restrict__ cursor,
                                  float* __restrict__ dis) {
    int tid = threadIdx.x;
    int lane = tid & 31, warp = tid >> 5;
    int base = (blockIdx.x * 256 + tid) * 16;
    int vals[16];
    int s = 0;
#pragma unroll
    for (int i = 0; i < 16; i++) {
        int idx = base + i;
        vals[i] = (idx < n) ? cnt[idx] : 0;
        s += vals[i];
    }
    // intra-warp inclusive scan of per-thread sums
    int incl = s;
#pragma unroll
    for (int o = 1; o < 32; o <<= 1) {
        int t = __shfl_up_sync(0xffffffffu, incl, o);
        if (lane >= o) incl += t;
    }
    __shared__ int wsum[8];
    if (lane == 31) wsum[warp] = incl;
    __syncthreads();
    int woff = 0, total = 0;
#pragma unroll
    for (int w = 0; w < 8; w++) {
        if (w < warp) woff += wsum[w];
        total += wsum[w];
    }
    // publish block total (+1 sentinel); lookback over predecessors
    __shared__ int sPre;
    if (tid == 0) {
        atomicExch(&bsum[blockIdx.x], total + 1);
        int pre = 0;
        for (int w = 0; w < (int)blockIdx.x; w++) {
            int v;
            do { v = atomicAdd(&bsum[w], 0); } while (v == 0);
            pre += v - 1;
        }
        sPre = pre;
    }
    __syncthreads();
    int excl = sPre + woff + (incl - s);
#pragma unroll
    for (int i = 0; i < 16; i++) {
        int idx = base + i;
        if (idx < n) {
            rowptr[idx] = excl;
            cursor[idx] = excl;
            dis[idx] = rsqrtf((float)(vals[i] + 1));
            excl += vals[i];
        }
    }
    if (blockIdx.x == gridDim.x - 1 && tid == 0) rowptr[n] = sPre + total;
}

__global__ void fill_kernel(const int* __restrict__ src, const int* __restrict__ dst, int e,
                            int* __restrict__ cursor, int* __restrict__ csrsrc,
                            float* __restrict__ csrnorm, const float* __restrict__ dis) {
    int i = blockIdx.x * blockDim.x + threadIdx.x;
    if (i >= e) return;
    int d = dst[i], s = src[i];
    int p = atomicAdd(&cursor[d], 1);
    csrsrc[p] = s;
    csrnorm[p] = dis[s] * dis[d];
}

// ---------------- merged weight + x conversion ----------------
__global__ void conv_kernel(const float* __restrict__ W1, const float* __restrict__ W3,
                            const float* __restrict__ W2, const float* __restrict__ W4,
                            const float* __restrict__ W7, const float* __restrict__ b1,
                            const float* __restrict__ b3, const float* __restrict__ x,
                            __half* WcT, __half* W2T, __half* W4T, __half* W7T,
                            float* bc, __half* xh, __half* Vf, int xtotal) {
    int i = blockIdx.x * blockDim.x + threadIdx.x;
    if (i < 256) bc[i] = (i < 128) ? b1[i] : b3[i - 128];
    if (i < 122880) {  // weights
        float v;
        __half* o;
        int off;
        if (i < 16384) {
            int c = i >> 6, k = i & 63;
            v = (c < 128) ? W1[k * 128 + c] : W3[k * 128 + (c - 128)];
            o = WcT; off = i;
        } else if (i < 49152) {
            int j = i - 16384; int c = j >> 7, k = j & 127;
            v = W2[k * 256 + c]; o = W2T; off = j;
        } else if (i < 81920) {
            int j = i - 49152; int c = j >> 7, k = j & 127;
            v = W4[k * 256 + c]; o = W4T; off = j;
        } else {
            int j = i - 81920; int c = j / 320, k = j % 320;
            v = (k < 256) ? W7[(size_t)(256 + k) * 128 + c]
                          : W7[(size_t)(512 + (k - 256)) * 128 + c];
            o = W7T; off = j;
        }
        o[off] = __float2half_rn(v);
    } else {           // x conversion
        int j = i - 122880;
        if (j >= xtotal) return;
        int row = j >> 6, c = j & 63;
        __half h = __float2half_rn(x[j]);
        xh[j] = h;
        Vf[(size_t)row * 320 + 256 + c] = h;
    }
}

// ---------------- HMMA mainloop (pure fp16) ----------------
__device__ __forceinline__ void gemm_mainloop(
    const __half* __restrict__ A, int lda,
    const __half* __restrict__ B,
    int K, int n, int rowBase, int colBase,
    __half (*As)[128 * 40], __half (*Bs)[128 * 40],
    float acc[4][4][4]) {
    int tid = threadIdx.x;
    int lane = tid & 31, warp = tid >> 5;
    int warpM = warp & 1, warpN = warp >> 1;
    int total = K >> 5;

    auto loadChunk = [&](int kc, int buf) {
        int k0 = kc << 5;
        uint32_t aB = smem_u32(&As[buf][0]);
        uint32_t bB = smem_u32(&Bs[buf][0]);
#pragma unroll
        for (int i = 0; i < 2; i++) {
            int idx = tid + (i << 8);
            int row = idx >> 2, quad = idx & 3;
            cpasync16(aB + (row * 40 + quad * 8) * 2,
                      A + (size_t)(rowBase + row) * lda + k0 + quad * 8,
                      (rowBase + row) < n);
            cpasync16(bB + (row * 40 + quad * 8) * 2,
                      B + (size_t)(colBase + row) * K + k0 + quad * 8, true);
        }
        asm volatile("cp.async.commit_group;");
    };

    auto compute = [&](int buf) {
        uint32_t aB = smem_u32(&As[buf][0]);
        uint32_t bB = smem_u32(&Bs[buf][0]);
#pragma unroll
        for (int ks = 0; ks < 2; ks++) {
            uint32_t af[4][4], bf[4][2];
            int arow = warpM * 64 + (lane & 15);
            int acol = ks * 16 + (lane >> 4) * 8;
#pragma unroll
            for (int mi = 0; mi < 4; mi++)
                ldmx4(af[mi][0], af[mi][1], af[mi][2], af[mi][3],
                      aB + ((arow + mi * 16) * 40 + acol) * 2);
#pragma unroll
            for (int np = 0; np < 2; np++) {
                int brow = warpN * 32 + np * 16 + (lane & 7) + ((lane >> 4) << 3);
                int bcol = ks * 16 + (((lane >> 3) & 1) << 3);
                ldmx4(bf[np * 2][0], bf[np * 2][1], bf[np * 2 + 1][0], bf[np * 2 + 1][1],
                      bB + (brow * 40 + bcol) * 2);
            }
#pragma unroll
            for (int mi = 0; mi < 4; mi++)
#pragma unroll
                for (int ni = 0; ni < 4; ni++) mma16816(acc[mi][ni], af[mi], bf[ni]);
        }
    };

    loadChunk(0, 0);
    for (int tc = 0; tc < total; tc++) {
        int buf = tc & 1;
        if (tc + 1 < total) {
            loadChunk(tc + 1, buf ^ 1);
            asm volatile("cp.async.wait_group 1;");
        } else {
            asm volatile("cp.async.wait_group 0;");
        }
        __syncthreads();
        compute(buf);
        __syncthreads();
    }
}

// ---------------- epilogues ----------------
__device__ __forceinline__ void epi_colmax(float acc[4][4][4], int n, int rBase, int cBase,
                                           int lane, const float* __restrict__ addvec,
                                           int* __restrict__ mv) {
    float cm[8];
#pragma unroll
    for (int j = 0; j < 8; j++) cm[j] = -1e30f;
#pragma unroll
    for (int mi = 0; mi < 4; mi++) {
        int r0 = rBase + mi * 16 + (lane >> 2);
        int r1 = r0 + 8;
#pragma unroll
        for (int ni = 0; ni < 4; ni++) {
            int col = cBase + ni * 8 + (lane & 3) * 2;
            float v0 = (r0 < n) ? tanhf(acc[mi][ni][0] + addvec[col]) : -1e30f;
            float v1 = (r0 < n) ? tanhf(acc[mi][ni][1] + addvec[col + 1]) : -1e30f;
            float v2 = (r1 < n) ? tanhf(acc[mi][ni][2] + addvec[col]) : -1e30f;
            float v3 = (r1 < n) ? tanhf(acc[mi][ni][3] + addvec[col + 1]) : -1e30f;
            cm[ni * 2] = fmaxf(cm[ni * 2], fmaxf(v0, v2));
            cm[ni * 2 + 1] = fmaxf(cm[ni * 2 + 1], fmaxf(v1, v3));
        }
    }
#pragma unroll
    for (int off = 4; off < 32; off <<= 1)
#pragma unroll
        for (int j = 0; j < 8; j++)
            cm[j] = fmaxf(cm[j], __shfl_xor_sync(0xffffffffu, cm[j], off));
    if (lane < 4) {
#pragma unroll
        for (int ni = 0; ni < 4; ni++) {
            int col = cBase + ni * 8 + lane * 2;
            atomicMax(&mv[col], __float_as_int(cm[ni * 2] + 2.0f));
            atomicMax(&mv[col + 1], __float_as_int(cm[ni * 2 + 1] + 2.0f));
        }
    }
}

// MODE 0: tanh(acc+addvec) -> half | MODE 1: acc+addvec -> half
template <int MODE>
__device__ __forceinline__ void epi_store_h(float acc[4][4][4], int n, int rBase, int cBase,
                                            int lane, const float* __restrict__ addvec,
                                            __half* __restrict__ outH, int ldO) {
#pragma unroll
    for (int mi = 0; mi < 4; mi++) {
#pragma unroll
        for (int h = 0; h < 2; h++) {
            int r = rBase + mi * 16 + (lane >> 2) + h * 8;
            if (r >= n) continue;
#pragma unroll
            for (int ni = 0; ni < 4; ni++) {
                int col = cBase + ni * 8 + (lane & 3) * 2;
                float v0 = acc[mi][ni][h * 2] + addvec[col];
                float v1 = acc[mi][ni][h * 2 + 1] + addvec[col + 1];
                if (MODE == 0) { v0 = tanhf(v0); v1 = tanhf(v1); }
                *(__half2*)(outH + (size_t)r * ldO + col) =
                    __halves2half2(__float2half_rn(v0), __float2half_rn(v1));
            }
        }
    }
}

// ---------------- GEMM 1: T1 = tanh(agg0 @ WcT + bc) ----------------
__global__ __launch_bounds__(256)
void hmma_gemm1(const __half* __restrict__ A, int lda, const __half* __restrict__ B,
                int K, int n, __half* __restrict__ outH, int ldO,
                const float* __restrict__ addvec) {
    __shared__ __align__(16) __half As[2][128 * 40];
    __shared__ __align__(16) __half Bs[2][128 * 40];
    float acc[4][4][4];
#pragma unroll
    for (int a = 0; a < 4; a++)
#pragma unroll
        for (int b = 0; b < 4; b++)
#pragma unroll
            for (int c = 0; c < 4; c++) acc[a][b][c] = 0.0f;
    int rowBase = blockIdx.x * 128, colBase = blockIdx.y * 128;
    gemm_mainloop(A, lda, B, K, n, rowBase, colBase, As, Bs, acc);
    int lane = threadIdx.x & 31, warp = threadIdx.x >> 5;
    int rBase = rowBase + (warp & 1) * 64, cBase = colBase + (warp >> 1) * 32;
    epi_store_h<0>(acc, n, rBase, cBase, lane, addvec, outH, ldO);
}

// ---------------- GEMM 7: H = [V|xh] @ W7T + cvec (cvec computed in-kernel) ----
__global__ __launch_bounds__(256)
void hmma_gemm7(const __half* __restrict__ A, int lda, const __half* __restrict__ B,
                int K, int n, __half* __restrict__ outH, int ldO,
                const int* __restrict__ mv, const float* __restrict__ W7) {
    __shared__ __align__(16) __half As[2][128 * 40];
    __shared__ __align__(16) __half Bs[2][128 * 40];
    __shared__ float sAdd[128];
    int tid = threadIdx.x;
    if (tid < 128) {  // cvec = (colmax) @ W7[0:256,:]
        float s = 0.0f;
        for (int k = 0; k < 256; k++)
            s += (__int_as_float(mv[k]) - 2.0f) * W7[(size_t)k * 128 + tid];
        sAdd[tid] = s;
    }
    float acc[4][4][4];
#pragma unroll
    for (int a = 0; a < 4; a++)
#pragma unroll
        for (int b = 0; b < 4; b++)
#pragma unroll
            for (int c = 0; c < 4; c++) acc[a][b][c] = 0.0f;
    int rowBase = blockIdx.x * 128, colBase = 0;
    gemm_mainloop(A, lda, B, K, n, rowBase, colBase, As, Bs, acc);
    int lane = tid & 31, warp = tid >> 5;
    int rBase = rowBase + (warp & 1) * 64, cBase = (warp >> 1) * 32;
    epi_store_h<1>(acc, n, rBase, cBase, lane, sAdd, outH, ldO);
}

// ---------------- merged U/V GEMM (z=0: colmax; z=1: V -> half) ----------------
__global__ __launch_bounds__(256)
void hmma_gemm_uv(const __half* __restrict__ agg1,
                  const __half* __restrict__ W2T, const __half* __restrict__ W4T,
                  int n, const float* __restrict__ b2, const float* __restrict__ b4,
                  __half* __restrict__ Vf, int* __restrict__ mv) {
    __shared__ __align__(16) __half As[2][128 * 40];
    __shared__ __align__(16) __half Bs[2][128 * 40];
    float acc[4][4][4];
#pragma unroll
    for (int a = 0; a < 4; a++)
#pragma unroll
        for (int b = 0; b < 4; b++)
#pragma unroll
            for (int c = 0; c < 4; c++) acc[a][b][c] = 0.0f;
    int z = blockIdx.z;
    const __half* A = agg1 + (z ? 128 : 0);
    const __half* B = z ? W4T : W2T;
    int rowBase = blockIdx.x * 128, colBase = blockIdx.y * 128;
    gemm_mainloop(A, 256, B, 128, n, rowBase, colBase, As, Bs, acc);
    int lane = threadIdx.x & 31, warp = threadIdx.x >> 5;
    int rBase = rowBase + (warp & 1) * 64, cBase = colBase + (warp >> 1) * 32;
    if (z == 0) {
        epi_colmax(acc, n, rBase, cBase, lane, b2, mv);
    } else {
        epi_store_h<0>(acc, n, rBase, cBase, lane, b4, Vf, 320);
    }
}

// ---------------- agg F=64 ----------------
__global__ void agg64_kernel(const __half* __restrict__ h, const int* __restrict__ rowptr,
                             const int* __restrict__ csrsrc, const float* __restrict__ csrnorm,
                             const float* __restrict__ dis, __half* __restrict__ out, int n) {
    int warp = (blockIdx.x * blockDim.x + threadIdx.x) >> 5;
    int lane = threadIdx.x & 31;
    if (warp >= n) return;
    float2 acc = make_float2(0.f, 0.f);
    int s0 = rowptr[warp], s1 = rowptr[warp + 1];
    int j = s0;
    for (; j + 1 < s1; j += 2) {
        int sa = csrsrc[j], sb = csrsrc[j + 1];
        float wa = csrnorm[j], wb = csrnorm[j + 1];
        float2 va = __half22float2(*(const __half2*)(h + (size_t)sa * 64 + lane * 2));
        float2 vb = __half22float2(*(const __half2*)(h + (size_t)sb * 64 + lane * 2));
        acc.x += va.x * wa + vb.x * wb;
        acc.y += va.y * wa + vb.y * wb;
    }
    if (j < s1) {
        int s = csrsrc[j];
        float w = csrnorm[j];
        float2 va = __half22float2(*(const __half2*)(h + (size_t)s * 64 + lane * 2));
        acc.x += va.x * w;
        acc.y += va.y * w;
    }
    float ds = dis[warp];
    float w2 = ds * ds;
    float2 v = __half22float2(*(const __half2*)(h + (size_t)warp * 64 + lane * 2));
    acc.x += v.x * w2;
    acc.y += v.y * w2;
    *(__half2*)(out + (size_t)warp * 64 + lane * 2) =
        __halves2half2(__float2half_rn(acc.x), __float2half_rn(acc.y));
}

// ---------------- agg F=256 (edge-unrolled x2) ----------------
__global__ void agg256_kernel(const __half* __restrict__ h, const int* __restrict__ rowptr,
                              const int* __restrict__ csrsrc, const float* __restrict__ csrnorm,
                              const float* __restrict__ dis, __half* __restrict__ out, int n) {
    int warp = (blockIdx.x * blockDim.x + threadIdx.x) >> 5;
    int lane = threadIdx.x & 31;
    if (warp >= n) return;
    float acc[8] = {0.f, 0.f, 0.f, 0.f, 0.f, 0.f, 0.f, 0.f};
    int s0 = rowptr[warp], s1 = rowptr[warp + 1];
    int i0 = lane * 8;
    int j = s0;
    for (; j + 1 < s1; j += 2) {
        int sa = csrsrc[j], sb = csrsrc[j + 1];
        float wa = csrnorm[j], wb = csrnorm[j + 1];
        uint4 ra = *(const uint4*)(h + (size_t)sa * 256 + i0);
        uint4 rb = *(const uint4*)(h + (size_t)sb * 256 + i0);
        const __half2* ha = (const __half2*)&ra;
        const __half2* hb = (const __half2*)&rb;
#pragma unroll
        for (int q = 0; q < 4; q++) {
            float2 fa = __half22float2(ha[q]);
            float2 fb = __half22float2(hb[q]);
            acc[q * 2] += fa.x * wa + fb.x * wb;
            acc[q * 2 + 1] += fa.y * wa + fb.y * wb;
        }
    }
    if (j < s1) {
        int s = csrsrc[j];
        float w = csrnorm[j];
        uint4 raw = *(const uint4*)(h + (size_t)s * 256 + i0);
        const __half2* hp = (const __half2*)&raw;
#pragma unroll
        for (int q = 0; q < 4; q++) {
            float2 f = __half22float2(hp[q]);
            acc[q * 2] += f.x * w;
            acc[q * 2 + 1] += f.y * w;
        }
    }
    float ds = dis[warp];
    float w2 = ds * ds;
    uint4 raw = *(const uint4*)(h + (size_t)warp * 256 + i0);
    const __half2* hp = (const __half2*)&raw;
#pragma unroll
    for (int q = 0; q < 4; q++) {
        float2 f = __half22float2(hp[q]);
        acc[q * 2] += f.x * w2;
        acc[q * 2 + 1] += f.y * w2;
    }
    uint4 o;
    __half2* op = (__half2*)&o;
#pragma unroll
    for (int q = 0; q < 4; q++)
        op[q] = __halves2half2(__float2half_rn(acc[q * 2]), __float2half_rn(acc[q * 2 + 1]));
    *(uint4*)(out + (size_t)warp * 256 + i0) = o;
}

// ---------------- agg F=128 + bias + tanh (final, fp32 out) ----------------
__global__ void agg128t_kernel(const __half* __restrict__ h, const int* __restrict__ rowptr,
                               const int* __restrict__ csrsrc, const float* __restrict__ csrnorm,
                               const float* __restrict__ dis, const float* __restrict__ bias,
                               float* __restrict__ out, int n) {
    int warp = (blockIdx.x * blockDim.x + threadIdx.x) >> 5;
    int lane = threadIdx.x & 31;
    if (warp >= n) return;
    float4 acc = make_float4(0.f, 0.f, 0.f, 0.f);
    int s0 = rowptr[warp], s1 = rowptr[warp + 1];
    int idx = lane << 2;
    int j = s0;
    for (; j + 1 < s1; j += 2) {
        int sa = csrsrc[j], sb = csrsrc[j + 1];
        float wa = csrnorm[j], wb = csrnorm[j + 1];
        uint2 ra = *(const uint2*)(h + (size_t)sa * 128 + idx);
        uint2 rb = *(const uint2*)(h + (size_t)sb * 128 + idx);
        float2 a0 = __half22float2(*(const __half2*)&ra.x);
        float2 a1 = __half22float2(*(const __half2*)&ra.y);
        float2 b0 = __half22float2(*(const __half2*)&rb.x);
        float2 b1 = __half22float2(*(const __half2*)&rb.y);
        acc.x += a0.x * wa + b0.x * wb;
        acc.y += a0.y * wa + b0.y * wb;
        acc.z += a1.x * wa + b1.x * wb;
        acc.w += a1.y * wa + b1.y * wb;
    }
    if (j < s1) {
        int s = csrsrc[j];
        float w = csrnorm[j];
        uint2 ra = *(const uint2*)(h + (size_t)s * 128 + idx);
        float2 a0 = __half22float2(*(const __half2*)&ra.x);
        float2 a1 = __half22float2(*(const __half2*)&ra.y);
        acc.x += a0.x * w; acc.y += a0.y * w; acc.z += a1.x * w; acc.w += a1.y * w;
    }
    float ds = dis[warp];
    float w2 = ds * ds;
    uint2 rv = *(const uint2*)(h + (size_t)warp * 128 + idx);
    float2 v0 = __half22float2(*(const __half2*)&rv.x);
    float2 v1 = __half22float2(*(const __half2*)&rv.y);
    float4 bb = *(const float4*)(bias + idx);
    float4 r;
    r.x = tanhf(acc.x + v0.x * w2 + bb.x);
    r.y = tanhf(acc.y + v0.y * w2 + bb.y);
    r.z = tanhf(acc.z + v1.x * w2 + bb.z);
    r.w = tanhf(acc.w + v1.y * w2 + bb.w);
    *(float4*)(out + (size_t)warp * 128 + idx) = r;
}

extern "C" void kernel_launch(void* const* d_in, const int* in_sizes, int n_in,
                              void* d_out, int out_size) {
    const float* x = (const float*)d_in[0];
    const int* ei = (const int*)d_in[1];
    const float* W1 = (const float*)d_in[3];
    const float* b1 = (const float*)d_in[4];
    const float* W2 = (const float*)d_in[5];
    const float* b2 = (const float*)d_in[6];
    const float* W3 = (const float*)d_in[7];
    const float* b3 = (const float*)d_in[8];
    const float* W4 = (const float*)d_in[9];
    const float* b4 = (const float*)d_in[10];
    const float* W7 = (const float*)d_in[11];
    const float* b7 = (const float*)d_in[12];

    int n = in_sizes[0] / 64;
    int e = in_sizes[1] / 2;
    const int* src = ei;
    const int* dst = ei + e;
    float* out = (float*)d_out;

    __half *xh, *agg0, *T1, *agg1, *Vf, *H, *WcT, *W2T, *W4T, *W7T;
    float *dis, *csrnorm, *bc;
    int *cnt, *rowptr, *cursor, *csrsrc, *mv, *bsum;
    cudaGetSymbolAddress((void**)&xh, g_xh);
    cudaGetSymbolAddress((void**)&agg0, g_agg0);
    cudaGetSymbolAddress((void**)&T1, g_T1);
    cudaGetSymbolAddress((void**)&agg1, g_agg1);
    cudaGetSymbolAddress((void**)&Vf, g_Vf);
    cudaGetSymbolAddress((void**)&H, g_H);
    cudaGetSymbolAddress((void**)&dis, g_dis);
    cudaGetSymbolAddress((void**)&cnt, g_cnt);
    cudaGetSymbolAddress((void**)&rowptr, g_rowptr);
    cudaGetSymbolAddress((void**)&cursor, g_cursor);
    cudaGetSymbolAddress((void**)&csrsrc, g_csrsrc);
    cudaGetSymbolAddress((void**)&csrnorm, g_csrnorm);
    cudaGetSymbolAddress((void**)&bsum, g_bsum);
    cudaGetSymbolAddress((void**)&mv, g_mv);
    cudaGetSymbolAddress((void**)&WcT, g_WcT);
    cudaGetSymbolAddress((void**)&W2T, g_W2T);
    cudaGetSymbolAddress((void**)&W4T, g_W4T);
    cudaGetSymbolAddress((void**)&W7T, g_W7T);
    cudaGetSymbolAddress((void**)&bc, g_bc);

    int eb = (e + 255) / 256;
    int aggBlocks = (n + 7) / 8;
    int gm = (n + 127) / 128;
    int nb = (n + 4095) / 4096;
    int convTotal = 122880 + n * 64;
    dim3 g2(gm, 2), guv(gm, 2, 2);

    // init + CSR build + conversions
    cudaMemsetAsync(cnt, 0, (size_t)n * sizeof(int));
    cudaMemsetAsync(bsum, 0, 64 * sizeof(int));
    cudaMemsetAsync(mv, 0, 256 * sizeof(int));
    conv_kernel<<<(convTotal + 255) / 256, 256>>>(W1, W3, W2, W4, W7, b1, b3, x,
                                                  WcT, W2T, W4T, W7T, bc, xh, Vf, n * 64);
    count_kernel<<<eb, 256>>>(dst, e, cnt);
    scan_fused_kernel<<<nb, 256>>>(cnt, n, bsum, rowptr, cursor, dis);
    fill_kernel<<<eb, 256>>>(src, dst, e, cursor, csrsrc, csrnorm, dis);

    // agg0 = P x
    agg64_kernel<<<aggBlocks, 256>>>(xh, rowptr, csrsrc, csrnorm, dis, agg0, n);
    // T1 = tanh(agg0 @ [W1|W3] + [b1|b3])
    hmma_gemm1<<<g2, 256>>>(agg0, 64, WcT, 64, n, T1, 256, bc);
    // agg1 = P T1
    agg256_kernel<<<aggBlocks, 256>>>(T1, rowptr, csrsrc, csrnorm, dis, agg1, n);
    // merged: z=0 colmax -> mv; z=1 V -> Vf
    hmma_gemm_uv<<<guv, 256>>>(agg1, W2T, W4T, n, b2, b4, Vf, mv);
    // H = [V|xh] @ W7T + cvec (cvec computed in-kernel from mv)
    hmma_gemm7<<<gm, 256>>>(Vf, 320, W7T, 320, n, H, 128, mv, W7);
    // out = tanh(P H + b7)
    agg128t_kernel<<<aggBlocks, 256>>>(H, rowptr, csrsrc, csrnorm, dis, b7, out, n);
}